// round 8
// baseline (speedup 1.0000x reference)
#include <cuda_runtime.h>
#include <cstdint>
#include <math.h>

#define DIMC   768
#define NHEADS 12
#define HDIM   64
#define BATCH  8
#define SEQ    1024
#define MROWS  (BATCH*SEQ)
#define PAIRS  (BATCH*NHEADS)
#define ATT_SCALE 0.125f

// ---------------- scratch (static device memory; no cudaMalloc allowed) ----
__device__ __align__(16) float g_Q   [(size_t)PAIRS*SEQ*HDIM];   // tf32-rounded
__device__ __align__(16) float g_K   [(size_t)PAIRS*SEQ*HDIM];   // tf32-rounded
__device__ __align__(16) float g_Vt  [(size_t)PAIRS*HDIM*SEQ];   // tf32-rounded, [pair][d][n]
__device__ __align__(16) float g_O   [(size_t)MROWS*DIMC];       // attn out, tf32-rounded
__device__ __align__(16) float g_Msig[(size_t)NHEADS*SEQ*SEQ];   // ATT_SCALE*sigmoid(mask)
__device__ __align__(16) float g_Xr  [(size_t)MROWS*DIMC];       // tf32(x)
__device__ __align__(16) float g_Wq  [(size_t)3*DIMC*DIMC];      // tf32(w_qkv)
__device__ __align__(16) float g_Wp  [(size_t)DIMC*DIMC];        // tf32(w_proj)

// ======================= helpers ===========================================
__device__ __forceinline__ uint32_t cvt_tf32(float x) {
    uint32_t r; asm("cvt.rna.tf32.f32 %0, %1;" : "=r"(r) : "f"(x)); return r;
}
__device__ __forceinline__ float tf32f(float x) {
    return __uint_as_float(cvt_tf32(x));
}
__device__ __forceinline__ void mma_tf32(float (&c)[4], const uint32_t (&a)[4],
                                         const uint32_t (&b)[2]) {
    asm volatile("mma.sync.aligned.m16n8k8.row.col.f32.tf32.tf32.f32 "
                 "{%0,%1,%2,%3}, {%4,%5,%6,%7}, {%8,%9}, {%0,%1,%2,%3};"
                 : "+f"(c[0]), "+f"(c[1]), "+f"(c[2]), "+f"(c[3])
                 : "r"(a[0]), "r"(a[1]), "r"(a[2]), "r"(a[3]),
                   "r"(b[0]), "r"(b[1]));
}
__device__ __forceinline__ uint32_t smem_u32(const void* p) {
    uint32_t a;
    asm("{ .reg .u64 t; cvta.to.shared.u64 t, %1; cvt.u32.u64 %0, t; }"
        : "=r"(a) : "l"(p));
    return a;
}
#define CP_ASYNC16(dst, src) \
    asm volatile("cp.async.cg.shared.global [%0], [%1], 16;" \
                 :: "r"(dst), "l"(src) : "memory")
#define CP_COMMIT() asm volatile("cp.async.commit_group;" ::: "memory")
#define CP_WAIT(n)  asm volatile("cp.async.wait_group %0;" :: "n"(n) : "memory")

// ============================================================================
// Rounding kernels — destinations are device globals referenced IN DEVICE CODE
// (passing __device__ arrays as host-side kernel args is invalid).
// ============================================================================
__device__ __forceinline__ void round_body(const float* __restrict__ src,
                                           float* __restrict__ dst) {
    size_t i = ((size_t)blockIdx.x * 256 + threadIdx.x) * 4;
    float4 v = *reinterpret_cast<const float4*>(src + i);
    v.x = tf32f(v.x); v.y = tf32f(v.y); v.z = tf32f(v.z); v.w = tf32f(v.w);
    *reinterpret_cast<float4*>(dst + i) = v;
}
__global__ __launch_bounds__(256) void round_x (const float* __restrict__ s) { round_body(s, g_Xr); }
__global__ __launch_bounds__(256) void round_wq(const float* __restrict__ s) { round_body(s, g_Wq); }
__global__ __launch_bounds__(256) void round_wp(const float* __restrict__ s) { round_body(s, g_Wp); }

__global__ __launch_bounds__(256) void presig(const float* __restrict__ m) {
    size_t i = ((size_t)blockIdx.x * 256 + threadIdx.x) * 4;
    float4 v = *reinterpret_cast<const float4*>(m + i);
    float4 o;
    o.x = ATT_SCALE / (1.f + __expf(-v.x));
    o.y = ATT_SCALE / (1.f + __expf(-v.y));
    o.z = ATT_SCALE / (1.f + __expf(-v.z));
    o.w = ATT_SCALE / (1.f + __expf(-v.w));
    *reinterpret_cast<float4*>(g_Msig + i) = o;
}

// ============================================================================
// NT GEMM core v2 (dynamic smem): cp.async 2-stage pipeline, operands tf32.
// C[128 x BN] = A[128 x K] * B[BN x K]^T.  256 threads, 8 warps.
// ============================================================================
#define LDK 36

template <int BN, int NC, int MF, int NF, int WMDIV>
__device__ __forceinline__ void gemm_core(const float* __restrict__ A, int lda,
                                          const float* __restrict__ B, int ldb,
                                          float (&acc)[MF][NF][4],
                                          float* smem) {
    float* As[2] = { smem, smem + 128 * LDK };
    float* Bs[2] = { smem + 2 * 128 * LDK, smem + 2 * 128 * LDK + BN * LDK };

    const int tid  = threadIdx.x;
    const int lane = tid & 31;
    const int wid  = tid >> 5;
    const int wm   = wid % WMDIV;
    const int wn   = wid / WMDIV;
    const int mrow0 = wm * (MF * 16);
    const int ncol0 = wn * (NF * 8);
    const int r = lane >> 2, q = lane & 3;

#pragma unroll
    for (int mf = 0; mf < MF; mf++)
#pragma unroll
        for (int nf = 0; nf < NF; nf++)
#pragma unroll
            for (int i = 0; i < 4; i++) acc[mf][nf][i] = 0.f;

    const int arow = tid >> 3, ac = (tid & 7) * 4;

    auto copy = [&](int i, int buf) {
        int k0 = i * 32;
#pragma unroll
        for (int p = 0; p < 4; p++) {
            int row = arow + p * 32;
            CP_ASYNC16(smem_u32(&As[buf][row * LDK + ac]),
                       A + (size_t)row * lda + k0 + ac);
        }
#pragma unroll
        for (int p = 0; p < BN / 32; p++) {
            int row = arow + p * 32;
            CP_ASYNC16(smem_u32(&Bs[buf][row * LDK + ac]),
                       B + (size_t)row * ldb + k0 + ac);
        }
    };

    copy(0, 0); CP_COMMIT();
    copy(1, 1); CP_COMMIT();
    CP_WAIT(1);
    __syncthreads();

#pragma unroll 1
    for (int i = 0; i < NC; i++) {
        const int buf = i & 1;
        const float* Ab = As[buf];
        const float* Bb = Bs[buf];
#pragma unroll
        for (int kk = 0; kk < 32; kk += 8) {
            uint32_t af[MF][4], bf[NF][2];
#pragma unroll
            for (int mf = 0; mf < MF; mf++) {
                const float* ap = &Ab[(mrow0 + mf * 16 + r) * LDK + kk + q];
                af[mf][0] = __float_as_uint(ap[0]);
                af[mf][1] = __float_as_uint(ap[8 * LDK]);
                af[mf][2] = __float_as_uint(ap[4]);
                af[mf][3] = __float_as_uint(ap[8 * LDK + 4]);
            }
#pragma unroll
            for (int nf = 0; nf < NF; nf++) {
                const float* bp = &Bb[(ncol0 + nf * 8 + r) * LDK + kk + q];
                bf[nf][0] = __float_as_uint(bp[0]);
                bf[nf][1] = __float_as_uint(bp[4]);
            }
#pragma unroll
            for (int mf = 0; mf < MF; mf++)
#pragma unroll
                for (int nf = 0; nf < NF; nf++)
                    mma_tf32(acc[mf][nf], af[mf], bf[nf]);
        }
        if (i == NC - 1) break;
        __syncthreads();
        if (i + 2 < NC) { copy(i + 2, buf); CP_COMMIT(); CP_WAIT(1); }
        else            { CP_WAIT(0); }
        __syncthreads();
    }
}

// ============================================================================
// Kernel 1: QKV projection + scatter to Q/K/Vt (stored tf32-rounded)
// ============================================================================
__global__ __launch_bounds__(256) void qkv_tc() {
    extern __shared__ float smf[];
    float acc[4][4][4];
    int brow = blockIdx.y * 128, bcol = blockIdx.x * 128;
    gemm_core<128, 24, 4, 4, 2>(g_Xr + (size_t)brow * DIMC, DIMC,
                                g_Wq + (size_t)bcol * DIMC, DIMC, acc, smf);
    int lane = threadIdx.x & 31, wid = threadIdx.x >> 5;
    int wm = wid % 2, wn = wid / 2, r = lane >> 2, q = lane & 3;
    int part = bcol / 768, rem0 = bcol - part * 768;

#pragma unroll
    for (int mf = 0; mf < 4; mf++)
#pragma unroll
        for (int nf = 0; nf < 4; nf++) {
            int col = rem0 + wn * 32 + nf * 8 + q * 2;
            int h = col >> 6, d = col & 63;
#pragma unroll
            for (int rr = 0; rr < 2; rr++) {
                int m = brow + wm * 64 + mf * 16 + r + rr * 8;
                int b = m >> 10, nq = m & 1023;
                float v0 = tf32f(acc[mf][nf][rr * 2 + 0]);
                float v1 = tf32f(acc[mf][nf][rr * 2 + 1]);
                if (part < 2) {
                    float* dst = (part == 0) ? g_Q : g_K;
                    *reinterpret_cast<float2*>(
                        &dst[(((size_t)(b * NHEADS + h)) * SEQ + nq) * HDIM + d]) =
                        make_float2(v0, v1);
                } else {
                    size_t pb = ((size_t)(b * NHEADS + h)) * HDIM;
                    g_Vt[(pb + d)     * SEQ + nq] = v0;
                    g_Vt[(pb + d + 1) * SEQ + nq] = v1;
                }
            }
        }
}

// ============================================================================
// Kernel 2: FUSED flash attention, 3-stage cp.async ring, 1 sync per k-iter.
// ============================================================================
#define KT 64
#define LDP 68
#define NITER (SEQ / KT)
#define STAGE_F (2 * 64 * LDP)

__global__ __launch_bounds__(256) void flash_tc() {
    extern __shared__ float sm[];
    float* Ps = sm + 3 * STAGE_F;

    const int tid = threadIdx.x, lane = tid & 31, wid = tid >> 5;
    const int r = lane >> 2, q = lane & 3;
    const int pair = blockIdx.y;
    const int h = pair % NHEADS, b = pair / NHEADS;
    const int q0 = blockIdx.x * 128;

    const float* Qg = g_Q  + (size_t)pair * SEQ * HDIM + (size_t)q0 * HDIM;
    const float* Kg = g_K  + (size_t)pair * SEQ * HDIM;
    const float* Vg = g_Vt + (size_t)pair * HDIM * SEQ;
    const float* Mg = g_Msig + (size_t)h * SEQ * SEQ;

    const int crow = tid >> 4, cc = (tid & 15) * 4;

    auto copyKV = [&](int kb, int buf) {
        float* Kd = sm + buf * STAGE_F;
        float* Vd = Kd + 64 * LDP;
        const float* Ksrc = Kg + (size_t)kb * KT * HDIM;
        const float* Vsrc = Vg + kb * KT;
#pragma unroll
        for (int p = 0; p < 4; p++) {
            int row = crow + p * 16;
            CP_ASYNC16(smem_u32(&Kd[row * LDP + cc]), Ksrc + (size_t)row * HDIM + cc);
            CP_ASYNC16(smem_u32(&Vd[row * LDP + cc]), Vsrc + (size_t)row * SEQ + cc);
        }
    };

    // ---- prologue ----
#pragma unroll
    for (int p = 0; p < 8; p++) {
        int row = crow + p * 16;
        CP_ASYNC16(smem_u32(&Ps[row * LDP + cc]), Qg + (size_t)row * HDIM + cc);
    }
    copyKV(0, 0);
    CP_COMMIT();
    copyKV(1, 1);
    CP_COMMIT();
    CP_WAIT(1);
    __syncthreads();

    uint32_t qa[8][4];
#pragma unroll
    for (int kk = 0; kk < 8; kk++) {
        const float* ap = &Ps[(wid * 16 + r) * LDP + kk * 8 + q];
        qa[kk][0] = __float_as_uint(ap[0]);
        qa[kk][1] = __float_as_uint(ap[8 * LDP]);
        qa[kk][2] = __float_as_uint(ap[4]);
        qa[kk][3] = __float_as_uint(ap[8 * LDP + 4]);
    }

    float od[8][4];
#pragma unroll
    for (int nf = 0; nf < 8; nf++)
#pragma unroll
        for (int i = 0; i < 4; i++) od[nf][i] = 0.f;
    float m0 = -1e30f, m1 = -1e30f, l0 = 0.f, l1 = 0.f;

    const int row_s0 = q0 + wid * 16 + r;

#pragma unroll 1
    for (int kb = 0; kb < NITER; kb++) {
        if (kb == NITER - 1) { CP_WAIT(0); } else { CP_WAIT(1); }
        __syncthreads();
        if (kb + 2 < NITER) {
            copyKV(kb + 2, (kb + 2) % 3);
            CP_COMMIT();
        }

        const float* Ks = sm + (kb % 3) * STAGE_F;
        const float* Vs = Ks + 64 * LDP;

        float sacc[8][4];
#pragma unroll
        for (int nf = 0; nf < 8; nf++)
#pragma unroll
            for (int i = 0; i < 4; i++) sacc[nf][i] = 0.f;
#pragma unroll
        for (int kk = 0; kk < 8; kk++) {
#pragma unroll
            for (int nf = 0; nf < 8; nf++) {
                uint32_t bf[2];
                const float* bp = &Ks[(nf * 8 + r) * LDP + kk * 8 + q];
                bf[0] = __float_as_uint(bp[0]);
                bf[1] = __float_as_uint(bp[4]);
                mma_tf32(sacc[nf], qa[kk], bf);
            }
        }

        float mx0 = -1e30f, mx1 = -1e30f;
#pragma unroll
        for (int nf = 0; nf < 8; nf++) {
            int col = kb * KT + nf * 8 + 2 * q;
            float2 g0 = *reinterpret_cast<const float2*>(&Mg[(size_t)row_s0 * SEQ + col]);
            float2 g1 = *reinterpret_cast<const float2*>(&Mg[(size_t)(row_s0 + 8) * SEQ + col]);
            sacc[nf][0] *= g0.x;
            sacc[nf][1] *= g0.y;
            sacc[nf][2] *= g1.x;
            sacc[nf][3] *= g1.y;
            mx0 = fmaxf(mx0, fmaxf(sacc[nf][0], sacc[nf][1]));
            mx1 = fmaxf(mx1, fmaxf(sacc[nf][2], sacc[nf][3]));
        }
        mx0 = fmaxf(mx0, __shfl_xor_sync(0xffffffffu, mx0, 1));
        mx0 = fmaxf(mx0, __shfl_xor_sync(0xffffffffu, mx0, 2));
        mx1 = fmaxf(mx1, __shfl_xor_sync(0xffffffffu, mx1, 1));
        mx1 = fmaxf(mx1, __shfl_xor_sync(0xffffffffu, mx1, 2));

        float mn0 = fmaxf(m0, mx0), mn1 = fmaxf(m1, mx1);
        float sc0 = __expf(m0 - mn0), sc1 = __expf(m1 - mn1);
        m0 = mn0; m1 = mn1;
        l0 *= sc0; l1 *= sc1;
#pragma unroll
        for (int nf = 0; nf < 8; nf++) {
            od[nf][0] *= sc0; od[nf][1] *= sc0;
            od[nf][2] *= sc1; od[nf][3] *= sc1;
        }

        float ls0 = 0.f, ls1 = 0.f;
        float* prow0 = &Ps[(wid * 16 + r) * LDP + 2 * q];
        float* prow1 = prow0 + 8 * LDP;
#pragma unroll
        for (int nf = 0; nf < 8; nf++) {
            float p00 = __expf(sacc[nf][0] - m0);
            float p01 = __expf(sacc[nf][1] - m0);
            float p10 = __expf(sacc[nf][2] - m1);
            float p11 = __expf(sacc[nf][3] - m1);
            ls0 += p00 + p01; ls1 += p10 + p11;
            *reinterpret_cast<float2*>(prow0 + nf * 8) = make_float2(tf32f(p00), tf32f(p01));
            *reinterpret_cast<float2*>(prow1 + nf * 8) = make_float2(tf32f(p10), tf32f(p11));
        }
        l0 += ls0; l1 += ls1;
        __syncwarp();

#pragma unroll
        for (int kk = 0; kk < 8; kk++) {
            uint32_t af[4];
            const float* ap = &Ps[(wid * 16 + r) * LDP + kk * 8 + q];
            af[0] = __float_as_uint(ap[0]);
            af[1] = __float_as_uint(ap[8 * LDP]);
            af[2] = __float_as_uint(ap[4]);
            af[3] = __float_as_uint(ap[8 * LDP + 4]);
#pragma unroll
            for (int nf = 0; nf < 8; nf++) {
                uint32_t bf[2];
                const float* bp = &Vs[(nf * 8 + r) * LDP + kk * 8 + q];
                bf[0] = __float_as_uint(bp[0]);
                bf[1] = __float_as_uint(bp[4]);
                mma_tf32(od[nf], af, bf);
            }
        }
    }

    l0 += __shfl_xor_sync(0xffffffffu, l0, 1);
    l0 += __shfl_xor_sync(0xffffffffu, l0, 2);
    l1 += __shfl_xor_sync(0xffffffffu, l1, 1);
    l1 += __shfl_xor_sync(0xffffffffu, l1, 2);
    float inv0 = 1.f / l0, inv1 = 1.f / l1;

    size_t orow0 = (size_t)b * SEQ + q0 + wid * 16 + r;
#pragma unroll
    for (int nf = 0; nf < 8; nf++) {
        int col = h * HDIM + nf * 8 + 2 * q;
        *reinterpret_cast<float2*>(&g_O[orow0 * DIMC + col]) =
            make_float2(tf32f(od[nf][0] * inv0), tf32f(od[nf][1] * inv0));
        *reinterpret_cast<float2*>(&g_O[(orow0 + 8) * DIMC + col]) =
            make_float2(tf32f(od[nf][2] * inv1), tf32f(od[nf][3] * inv1));
    }
}

// ============================================================================
// Kernel 3: out = O @ Wproj^T + bias
// ============================================================================
__global__ __launch_bounds__(256) void proj_tc(const float* __restrict__ bias,
                                               float* __restrict__ out) {
    extern __shared__ float smf[];
    float acc[4][4][4];
    int brow = blockIdx.y * 128, bcol = blockIdx.x * 128;
    gemm_core<128, 24, 4, 4, 2>(g_O + (size_t)brow * DIMC, DIMC,
                                g_Wp + (size_t)bcol * DIMC, DIMC, acc, smf);
    int lane = threadIdx.x & 31, wid = threadIdx.x >> 5;
    int wm = wid % 2, wn = wid / 2, r = lane >> 2, q = lane & 3;

#pragma unroll
    for (int mf = 0; mf < 4; mf++)
#pragma unroll
        for (int nf = 0; nf < 4; nf++) {
            int col = bcol + wn * 32 + nf * 8 + q * 2;
            float2 bb = *reinterpret_cast<const float2*>(&bias[col]);
#pragma unroll
            for (int rr = 0; rr < 2; rr++) {
                int row = brow + wm * 64 + mf * 16 + r + rr * 8;
                float v0 = acc[mf][nf][rr * 2 + 0] + bb.x;
                float v1 = acc[mf][nf][rr * 2 + 1] + bb.y;
                *reinterpret_cast<float2*>(&out[(size_t)row * DIMC + col]) = make_float2(v0, v1);
            }
        }
}

// ============================================================================
extern "C" void kernel_launch(void* const* d_in, const int* in_sizes, int n_in,
                              void* d_out, int out_size) {
    (void)in_sizes; (void)n_in; (void)out_size;
    const float* x        = (const float*)d_in[0];
    const float* w_qkv    = (const float*)d_in[1];
    const float* w_proj   = (const float*)d_in[2];
    const float* b_proj   = (const float*)d_in[3];
    const float* att_mask = (const float*)d_in[4];
    float* out = (float*)d_out;

    const int GEMM_SMEM  = (4 * 128 * LDK) * (int)sizeof(float);           // 73728
    const int FLASH_SMEM = (3 * STAGE_F + 128 * LDP) * (int)sizeof(float); // 139264

    cudaFuncSetAttribute(qkv_tc,   cudaFuncAttributeMaxDynamicSharedMemorySize, GEMM_SMEM);
    cudaFuncSetAttribute(proj_tc,  cudaFuncAttributeMaxDynamicSharedMemorySize, GEMM_SMEM);
    cudaFuncSetAttribute(flash_tc, cudaFuncAttributeMaxDynamicSharedMemorySize, FLASH_SMEM);

    round_x <<<(MROWS * DIMC) / 1024, 256>>>(x);
    round_wq<<<(3 * DIMC * DIMC) / 1024, 256>>>(w_qkv);
    round_wp<<<(DIMC * DIMC) / 1024, 256>>>(w_proj);
    presig  <<<(NHEADS * SEQ * SEQ) / 1024, 256>>>(att_mask);

    qkv_tc  <<<dim3(2304 / 128, MROWS / 128), 256, GEMM_SMEM>>>();
    flash_tc<<<dim3(SEQ / 128, PAIRS), 256, FLASH_SMEM>>>();
    proj_tc <<<dim3(DIMC / 128, MROWS / 128), 256, GEMM_SMEM>>>(b_proj, out);
}

// round 9
// speedup vs baseline: 1.5031x; 1.5031x over previous
#include <cuda_runtime.h>
#include <cstdint>
#include <math.h>

#define DIMC   768
#define NHEADS 12
#define HDIM   64
#define BATCH  8
#define SEQ    1024
#define MROWS  (BATCH*SEQ)
#define PAIRS  (BATCH*NHEADS)
#define ATT_SCALE 0.125f

// ---------------- scratch (static device memory; no cudaMalloc allowed) ----
// g_Q/g_K: tf32-rounded, d-dim sigma-permuted within groups of 8
// g_Vt   : tf32-rounded, [pair][d][key], plain key order
// g_O    : tf32-rounded, k-dim sigma-permuted (for proj)
// g_Xr/g_Wq/g_Wp: tf32-rounded, k-dim sigma-permuted
__device__ __align__(16) float g_Q   [(size_t)PAIRS*SEQ*HDIM];
__device__ __align__(16) float g_K   [(size_t)PAIRS*SEQ*HDIM];
__device__ __align__(16) float g_Vt  [(size_t)PAIRS*HDIM*SEQ];
__device__ __align__(16) float g_O   [(size_t)MROWS*DIMC];
__device__ __align__(16) float g_Msig[(size_t)NHEADS*SEQ*SEQ];
__device__ __align__(16) float g_Xr  [(size_t)MROWS*DIMC];
__device__ __align__(16) float g_Wq  [(size_t)3*DIMC*DIMC];
__device__ __align__(16) float g_Wp  [(size_t)DIMC*DIMC];

// ======================= helpers ===========================================
__device__ __forceinline__ uint32_t cvt_tf32(float x) {
    uint32_t r; asm("cvt.rna.tf32.f32 %0, %1;" : "=r"(r) : "f"(x)); return r;
}
__device__ __forceinline__ float tf32f(float x) {
    return __uint_as_float(cvt_tf32(x));
}
__device__ __forceinline__ int sig8(int j) {           // 0,2,4,6,1,3,5,7 inverse-interleave
    return ((j & 3) << 1) | (j >> 2);
}
__device__ __forceinline__ void mma_tf32(float (&c)[4], const uint32_t (&a)[4],
                                         const uint32_t (&b)[2]) {
    asm volatile("mma.sync.aligned.m16n8k8.row.col.f32.tf32.tf32.f32 "
                 "{%0,%1,%2,%3}, {%4,%5,%6,%7}, {%8,%9}, {%0,%1,%2,%3};"
                 : "+f"(c[0]), "+f"(c[1]), "+f"(c[2]), "+f"(c[3])
                 : "r"(a[0]), "r"(a[1]), "r"(a[2]), "r"(a[3]),
                   "r"(b[0]), "r"(b[1]));
}
__device__ __forceinline__ uint32_t smem_u32(const void* p) {
    uint32_t a;
    asm("{ .reg .u64 t; cvta.to.shared.u64 t, %1; cvt.u32.u64 %0, t; }"
        : "=r"(a) : "l"(p));
    return a;
}
#define CP_ASYNC16(dst, src) \
    asm volatile("cp.async.cg.shared.global [%0], [%1], 16;" \
                 :: "r"(dst), "l"(src) : "memory")
#define CP_COMMIT() asm volatile("cp.async.commit_group;" ::: "memory")
#define CP_WAIT(n)  asm volatile("cp.async.wait_group %0;" :: "n"(n) : "memory")

// ============================================================================
// Pre-kernels: tf32 rounding + sigma-permutation of k-dim columns (DIMC wide)
// ============================================================================
__device__ __forceinline__ void round_perm_body(const float* __restrict__ src,
                                                float* __restrict__ dst) {
    size_t i = ((size_t)blockIdx.x * 256 + threadIdx.x) * 4;
    float4 v = *reinterpret_cast<const float4*>(src + i);
    int col = (int)(i % DIMC);                 // multiple of 4
    size_t rowbase = i - col;
    int cb = (col & ~7) + ((col & 4) ? 1 : 0); // sigma of first of the 4
    dst[rowbase + cb]     = tf32f(v.x);
    dst[rowbase + cb + 2] = tf32f(v.y);
    dst[rowbase + cb + 4] = tf32f(v.z);
    dst[rowbase + cb + 6] = tf32f(v.w);
}
__global__ __launch_bounds__(256) void round_x (const float* __restrict__ s) { round_perm_body(s, g_Xr); }
__global__ __launch_bounds__(256) void round_wq(const float* __restrict__ s) { round_perm_body(s, g_Wq); }
__global__ __launch_bounds__(256) void round_wp(const float* __restrict__ s) { round_perm_body(s, g_Wp); }

__global__ __launch_bounds__(256) void presig(const float* __restrict__ m) {
    size_t i = ((size_t)blockIdx.x * 256 + threadIdx.x) * 4;
    float4 v = *reinterpret_cast<const float4*>(m + i);
    float4 o;
    o.x = ATT_SCALE / (1.f + __expf(-v.x));
    o.y = ATT_SCALE / (1.f + __expf(-v.y));
    o.z = ATT_SCALE / (1.f + __expf(-v.z));
    o.w = ATT_SCALE / (1.f + __expf(-v.w));
    *reinterpret_cast<float4*>(g_Msig + i) = o;
}

// ============================================================================
// NT GEMM core v3: cp.async 2-stage, LDK=40 (8 mod 32), LDS.64 fragment loads
// (operands tf32-rounded AND sigma-permuted along k). 256 threads, 8 warps.
// ============================================================================
#define LDK 40

template <int BN, int NC, int MF, int NF, int WMDIV>
__device__ __forceinline__ void gemm_core(const float* __restrict__ A, int lda,
                                          const float* __restrict__ B, int ldb,
                                          float (&acc)[MF][NF][4],
                                          float* smem) {
    float* As[2] = { smem, smem + 128 * LDK };
    float* Bs[2] = { smem + 2 * 128 * LDK, smem + 2 * 128 * LDK + BN * LDK };

    const int tid  = threadIdx.x;
    const int lane = tid & 31;
    const int wid  = tid >> 5;
    const int wm   = wid % WMDIV;
    const int wn   = wid / WMDIV;
    const int mrow0 = wm * (MF * 16);
    const int ncol0 = wn * (NF * 8);
    const int r = lane >> 2, q = lane & 3;

#pragma unroll
    for (int mf = 0; mf < MF; mf++)
#pragma unroll
        for (int nf = 0; nf < NF; nf++)
#pragma unroll
            for (int i = 0; i < 4; i++) acc[mf][nf][i] = 0.f;

    const int arow = tid >> 3, ac = (tid & 7) * 4;

    auto copy = [&](int i, int buf) {
        int k0 = i * 32;
#pragma unroll
        for (int p = 0; p < 4; p++) {
            int row = arow + p * 32;
            CP_ASYNC16(smem_u32(&As[buf][row * LDK + ac]),
                       A + (size_t)row * lda + k0 + ac);
        }
#pragma unroll
        for (int p = 0; p < BN / 32; p++) {
            int row = arow + p * 32;
            CP_ASYNC16(smem_u32(&Bs[buf][row * LDK + ac]),
                       B + (size_t)row * ldb + k0 + ac);
        }
    };

    copy(0, 0); CP_COMMIT();
    copy(1, 1); CP_COMMIT();
    CP_WAIT(1);
    __syncthreads();

#pragma unroll 1
    for (int i = 0; i < NC; i++) {
        const int buf = i & 1;
        const float* Ab = As[buf];
        const float* Bb = Bs[buf];
#pragma unroll
        for (int kk = 0; kk < 32; kk += 8) {
            uint32_t af[MF][4], bf[NF][2];
#pragma unroll
            for (int mf = 0; mf < MF; mf++) {
                float2 a0 = *reinterpret_cast<const float2*>(
                    &Ab[(mrow0 + mf * 16 + r) * LDK + kk + 2 * q]);
                float2 a1 = *reinterpret_cast<const float2*>(
                    &Ab[(mrow0 + mf * 16 + r + 8) * LDK + kk + 2 * q]);
                af[mf][0] = __float_as_uint(a0.x);
                af[mf][1] = __float_as_uint(a1.x);
                af[mf][2] = __float_as_uint(a0.y);
                af[mf][3] = __float_as_uint(a1.y);
            }
#pragma unroll
            for (int nf = 0; nf < NF; nf++) {
                float2 b0 = *reinterpret_cast<const float2*>(
                    &Bb[(ncol0 + nf * 8 + r) * LDK + kk + 2 * q]);
                bf[nf][0] = __float_as_uint(b0.x);
                bf[nf][1] = __float_as_uint(b0.y);
            }
#pragma unroll
            for (int mf = 0; mf < MF; mf++)
#pragma unroll
                for (int nf = 0; nf < NF; nf++)
                    mma_tf32(acc[mf][nf], af[mf], bf[nf]);
        }
        if (i == NC - 1) break;
        __syncthreads();
        if (i + 2 < NC) { copy(i + 2, buf); CP_COMMIT(); CP_WAIT(1); }
        else            { CP_WAIT(0); }
        __syncthreads();
    }
}

// ============================================================================
// Kernel 1: QKV projection + scatter. Q/K stored d-sigma-permuted; V plain.
// ============================================================================
__global__ __launch_bounds__(256) void qkv_tc() {
    extern __shared__ float smf[];
    float acc[4][4][4];
    int brow = blockIdx.y * 128, bcol = blockIdx.x * 128;
    gemm_core<128, 24, 4, 4, 2>(g_Xr + (size_t)brow * DIMC, DIMC,
                                g_Wq + (size_t)bcol * DIMC, DIMC, acc, smf);
    int lane = threadIdx.x & 31, wid = threadIdx.x >> 5;
    int wm = wid % 2, wn = wid / 2, r = lane >> 2, q = lane & 3;
    int part = bcol / 768, rem0 = bcol - part * 768;
    int j0 = 2 * q;
    int s0 = sig8(j0), s1 = sig8(j0 + 1);

#pragma unroll
    for (int mf = 0; mf < 4; mf++)
#pragma unroll
        for (int nf = 0; nf < 4; nf++) {
            int col = rem0 + wn * 32 + nf * 8 + j0;
            int h = col >> 6, d = col & 63;
            int dbase = d - j0;                    // group base within head
#pragma unroll
            for (int rr = 0; rr < 2; rr++) {
                int m = brow + wm * 64 + mf * 16 + r + rr * 8;
                int b = m >> 10, nq = m & 1023;
                float v0 = tf32f(acc[mf][nf][rr * 2 + 0]);
                float v1 = tf32f(acc[mf][nf][rr * 2 + 1]);
                if (part < 2) {
                    float* dst = (part == 0) ? g_Q : g_K;
                    size_t base = (((size_t)(b * NHEADS + h)) * SEQ + nq) * HDIM;
                    dst[base + dbase + s0] = v0;
                    dst[base + dbase + s1] = v1;
                } else {
                    size_t pb = ((size_t)(b * NHEADS + h)) * HDIM;
                    g_Vt[(pb + d)     * SEQ + nq] = v0;
                    g_Vt[(pb + d + 1) * SEQ + nq] = v1;
                }
            }
        }
}

// ============================================================================
// Kernel 2: FUSED flash attention.
//  - 3-stage cp.async KV ring (110592 B smem, 2 CTAs/SM), 1 syncthreads/iter
//  - Q fragments loaded once from (permuted) global; P stays in registers
//    (S c-frag == PV a-frag under key order 0,2,4,6,1,3,5,7; V plain order)
//  - all smem fragment loads are conflict-free LDS.64 (stride 72)
// ============================================================================
#define KT 64
#define LDT 72
#define NITER (SEQ / KT)
#define STAGE_F (2 * 64 * LDT)

__global__ __launch_bounds__(256, 2) void flash_tc() {
    extern __shared__ float sm[];

    const int tid = threadIdx.x, lane = tid & 31, wid = tid >> 5;
    const int r = lane >> 2, q = lane & 3;
    const int pair = blockIdx.y;
    const int h = pair % NHEADS, b = pair / NHEADS;
    const int q0 = blockIdx.x * 128;

    const float* Qg = g_Q  + (size_t)pair * SEQ * HDIM;
    const float* Kg = g_K  + (size_t)pair * SEQ * HDIM;
    const float* Vg = g_Vt + (size_t)pair * HDIM * SEQ;
    const float* Mg = g_Msig + (size_t)h * SEQ * SEQ;

    const int crow = tid >> 4, cc = (tid & 15) * 4;

    auto copyKV = [&](int kb, int buf) {
        float* Kd = sm + buf * STAGE_F;
        float* Vd = Kd + 64 * LDT;
        const float* Ksrc = Kg + (size_t)(kb * KT) * HDIM;
        const float* Vsrc = Vg + kb * KT;
#pragma unroll
        for (int p = 0; p < 4; p++) {
            int row = crow + p * 16;
            CP_ASYNC16(smem_u32(&Kd[row * LDT + cc]), Ksrc + (size_t)row * HDIM + cc);
            CP_ASYNC16(smem_u32(&Vd[row * LDT + cc]), Vsrc + (size_t)row * SEQ + cc);
        }
    };

    copyKV(0, 0); CP_COMMIT();
    copyKV(1, 1); CP_COMMIT();

    // ---- Q fragments directly from permuted global (no staging) ----
    uint32_t qa[8][4];
    {
        const float* qr0 = Qg + (size_t)(q0 + wid * 16 + r) * HDIM;
        const float* qr1 = qr0 + 8 * HDIM;
#pragma unroll
        for (int kk = 0; kk < 8; kk++) {
            float2 v0 = *reinterpret_cast<const float2*>(qr0 + kk * 8 + 2 * q);
            float2 v1 = *reinterpret_cast<const float2*>(qr1 + kk * 8 + 2 * q);
            qa[kk][0] = __float_as_uint(v0.x);
            qa[kk][1] = __float_as_uint(v1.x);
            qa[kk][2] = __float_as_uint(v0.y);
            qa[kk][3] = __float_as_uint(v1.y);
        }
    }

    float od[8][4];
#pragma unroll
    for (int nf = 0; nf < 8; nf++)
#pragma unroll
        for (int i = 0; i < 4; i++) od[nf][i] = 0.f;
    float m0 = -1e30f, m1 = -1e30f, l0 = 0.f, l1 = 0.f;

    const int row_s0 = q0 + wid * 16 + r;

#pragma unroll 1
    for (int kb = 0; kb < NITER; kb++) {
        if (kb == NITER - 1) { CP_WAIT(0); } else { CP_WAIT(1); }
        __syncthreads();                 // stage kb visible; compute kb-1 done
        if (kb + 2 < NITER) {
            copyKV(kb + 2, (kb + 2) % 3);
            CP_COMMIT();
        }

        const float* Ks = sm + (kb % 3) * STAGE_F;
        const float* Vs = Ks + 64 * LDT;

        // ---- S = Q K^T (LDS.64 b-frags, conflict-free) ----
        float sacc[8][4];
#pragma unroll
        for (int nf = 0; nf < 8; nf++)
#pragma unroll
            for (int i = 0; i < 4; i++) sacc[nf][i] = 0.f;
#pragma unroll
        for (int kk = 0; kk < 8; kk++) {
#pragma unroll
            for (int nf = 0; nf < 8; nf++) {
                float2 bv = *reinterpret_cast<const float2*>(
                    &Ks[(nf * 8 + r) * LDT + kk * 8 + 2 * q]);
                uint32_t bf[2] = { __float_as_uint(bv.x), __float_as_uint(bv.y) };
                mma_tf32(sacc[nf], qa[kk], bf);
            }
        }

        // ---- gate + online softmax ----
        float mx0 = -1e30f, mx1 = -1e30f;
#pragma unroll
        for (int nf = 0; nf < 8; nf++) {
            int col = kb * KT + nf * 8 + 2 * q;
            float2 g0 = *reinterpret_cast<const float2*>(&Mg[(size_t)row_s0 * SEQ + col]);
            float2 g1 = *reinterpret_cast<const float2*>(&Mg[(size_t)(row_s0 + 8) * SEQ + col]);
            sacc[nf][0] *= g0.x;
            sacc[nf][1] *= g0.y;
            sacc[nf][2] *= g1.x;
            sacc[nf][3] *= g1.y;
            mx0 = fmaxf(mx0, fmaxf(sacc[nf][0], sacc[nf][1]));
            mx1 = fmaxf(mx1, fmaxf(sacc[nf][2], sacc[nf][3]));
        }
        mx0 = fmaxf(mx0, __shfl_xor_sync(0xffffffffu, mx0, 1));
        mx0 = fmaxf(mx0, __shfl_xor_sync(0xffffffffu, mx0, 2));
        mx1 = fmaxf(mx1, __shfl_xor_sync(0xffffffffu, mx1, 1));
        mx1 = fmaxf(mx1, __shfl_xor_sync(0xffffffffu, mx1, 2));

        float mn0 = fmaxf(m0, mx0), mn1 = fmaxf(m1, mx1);
        float sc0 = __expf(m0 - mn0), sc1 = __expf(m1 - mn1);
        m0 = mn0; m1 = mn1;
        l0 *= sc0; l1 *= sc1;
#pragma unroll
        for (int nf = 0; nf < 8; nf++) {
            od[nf][0] *= sc0; od[nf][1] *= sc0;
            od[nf][2] *= sc1; od[nf][3] *= sc1;
        }

        // ---- P in registers -> PV (a-frag = exp'd S c-frag; V plain order) --
        float ls0 = 0.f, ls1 = 0.f;
#pragma unroll
        for (int g = 0; g < 8; g++) {
            float p00 = __expf(sacc[g][0] - m0);
            float p01 = __expf(sacc[g][1] - m0);
            float p10 = __expf(sacc[g][2] - m1);
            float p11 = __expf(sacc[g][3] - m1);
            ls0 += p00 + p01; ls1 += p10 + p11;
            uint32_t af[4] = { cvt_tf32(p00), cvt_tf32(p10),
                               cvt_tf32(p01), cvt_tf32(p11) };
#pragma unroll
            for (int nf = 0; nf < 8; nf++) {
                float2 bv = *reinterpret_cast<const float2*>(
                    &Vs[(nf * 8 + r) * LDT + g * 8 + 2 * q]);
                uint32_t bf[2] = { __float_as_uint(bv.x), __float_as_uint(bv.y) };
                mma_tf32(od[nf], af, bf);
            }
        }
        l0 += ls0; l1 += ls1;
    }

    // ---- normalize and write O (tf32-rounded, k-sigma-permuted for proj) ----
    l0 += __shfl_xor_sync(0xffffffffu, l0, 1);
    l0 += __shfl_xor_sync(0xffffffffu, l0, 2);
    l1 += __shfl_xor_sync(0xffffffffu, l1, 1);
    l1 += __shfl_xor_sync(0xffffffffu, l1, 2);
    float inv0 = 1.f / l0, inv1 = 1.f / l1;

    size_t orow0 = (size_t)b * SEQ + q0 + wid * 16 + r;
    int j0 = 2 * q;
    int s0 = sig8(j0), s1 = sig8(j0 + 1);
#pragma unroll
    for (int nf = 0; nf < 8; nf++) {
        int cbase = h * HDIM + nf * 8;
        g_O[orow0 * DIMC + cbase + s0]       = tf32f(od[nf][0] * inv0);
        g_O[orow0 * DIMC + cbase + s1]       = tf32f(od[nf][1] * inv0);
        g_O[(orow0 + 8) * DIMC + cbase + s0] = tf32f(od[nf][2] * inv1);
        g_O[(orow0 + 8) * DIMC + cbase + s1] = tf32f(od[nf][3] * inv1);
    }
}

// ============================================================================
// Kernel 3: out = O @ Wproj^T + bias  (both operands k-permuted; output plain)
// ============================================================================
__global__ __launch_bounds__(256) void proj_tc(const float* __restrict__ bias,
                                               float* __restrict__ out) {
    extern __shared__ float smf[];
    float acc[4][4][4];
    int brow = blockIdx.y * 128, bcol = blockIdx.x * 128;
    gemm_core<128, 24, 4, 4, 2>(g_O + (size_t)brow * DIMC, DIMC,
                                g_Wp + (size_t)bcol * DIMC, DIMC, acc, smf);
    int lane = threadIdx.x & 31, wid = threadIdx.x >> 5;
    int wm = wid % 2, wn = wid / 2, r = lane >> 2, q = lane & 3;

#pragma unroll
    for (int mf = 0; mf < 4; mf++)
#pragma unroll
        for (int nf = 0; nf < 4; nf++) {
            int col = bcol + wn * 32 + nf * 8 + q * 2;
            float2 bb = *reinterpret_cast<const float2*>(&bias[col]);
#pragma unroll
            for (int rr = 0; rr < 2; rr++) {
                int row = brow + wm * 64 + mf * 16 + r + rr * 8;
                float v0 = acc[mf][nf][rr * 2 + 0] + bb.x;
                float v1 = acc[mf][nf][rr * 2 + 1] + bb.y;
                *reinterpret_cast<float2*>(&out[(size_t)row * DIMC + col]) = make_float2(v0, v1);
            }
        }
}

// ============================================================================
extern "C" void kernel_launch(void* const* d_in, const int* in_sizes, int n_in,
                              void* d_out, int out_size) {
    (void)in_sizes; (void)n_in; (void)out_size;
    const float* x        = (const float*)d_in[0];
    const float* w_qkv    = (const float*)d_in[1];
    const float* w_proj   = (const float*)d_in[2];
    const float* b_proj   = (const float*)d_in[3];
    const float* att_mask = (const float*)d_in[4];
    float* out = (float*)d_out;

    const int GEMM_SMEM  = (4 * 128 * LDK) * (int)sizeof(float);   // 81920
    const int FLASH_SMEM = (3 * STAGE_F) * (int)sizeof(float);     // 110592

    cudaFuncSetAttribute(qkv_tc,   cudaFuncAttributeMaxDynamicSharedMemorySize, GEMM_SMEM);
    cudaFuncSetAttribute(proj_tc,  cudaFuncAttributeMaxDynamicSharedMemorySize, GEMM_SMEM);
    cudaFuncSetAttribute(flash_tc, cudaFuncAttributeMaxDynamicSharedMemorySize, FLASH_SMEM);

    round_x <<<(MROWS * DIMC) / 1024, 256>>>(x);
    round_wq<<<(3 * DIMC * DIMC) / 1024, 256>>>(w_qkv);
    round_wp<<<(DIMC * DIMC) / 1024, 256>>>(w_proj);
    presig  <<<(NHEADS * SEQ * SEQ) / 1024, 256>>>(att_mask);

    qkv_tc  <<<dim3(2304 / 128, MROWS / 128), 256, GEMM_SMEM>>>();
    flash_tc<<<dim3(SEQ / 128, PAIRS), 256, FLASH_SMEM>>>();
    proj_tc <<<dim3(DIMC / 128, MROWS / 128), 256, GEMM_SMEM>>>(b_proj, out);
}

// round 10
// speedup vs baseline: 1.5577x; 1.0363x over previous
#include <cuda_runtime.h>
#include <cstdint>
#include <math.h>

#define DIMC   768
#define NHEADS 12
#define HDIM   64
#define BATCH  8
#define SEQ    1024
#define MROWS  (BATCH*SEQ)
#define PAIRS  (BATCH*NHEADS)
#define ATT_SCALE 0.125f

// ---------------- scratch (static device memory; no cudaMalloc allowed) ----
// g_Q/g_K: tf32-rounded, d-dim sigma-permuted within groups of 8
// g_Vt   : tf32-rounded, [pair][d][key], plain key order
// g_O    : tf32-rounded, k-dim sigma-permuted (for proj)
// g_Xr/g_Wq/g_Wp: tf32-rounded, k-dim sigma-permuted
__device__ __align__(16) float g_Q   [(size_t)PAIRS*SEQ*HDIM];
__device__ __align__(16) float g_K   [(size_t)PAIRS*SEQ*HDIM];
__device__ __align__(16) float g_Vt  [(size_t)PAIRS*HDIM*SEQ];
__device__ __align__(16) float g_O   [(size_t)MROWS*DIMC];
__device__ __align__(16) float g_Msig[(size_t)NHEADS*SEQ*SEQ];
__device__ __align__(16) float g_Xr  [(size_t)MROWS*DIMC];
__device__ __align__(16) float g_Wq  [(size_t)3*DIMC*DIMC];
__device__ __align__(16) float g_Wp  [(size_t)DIMC*DIMC];

// ======================= helpers ===========================================
__device__ __forceinline__ uint32_t cvt_tf32(float x) {
    uint32_t r; asm("cvt.rna.tf32.f32 %0, %1;" : "=r"(r) : "f"(x)); return r;
}
__device__ __forceinline__ float tf32f(float x) {
    return __uint_as_float(cvt_tf32(x));
}
__device__ __forceinline__ int sig8(int j) {           // 0,2,4,6,1,3,5,7
    return ((j & 3) << 1) | (j >> 2);
}
__device__ __forceinline__ void mma_tf32(float (&c)[4], const uint32_t (&a)[4],
                                         const uint32_t (&b)[2]) {
    asm volatile("mma.sync.aligned.m16n8k8.row.col.f32.tf32.tf32.f32 "
                 "{%0,%1,%2,%3}, {%4,%5,%6,%7}, {%8,%9}, {%0,%1,%2,%3};"
                 : "+f"(c[0]), "+f"(c[1]), "+f"(c[2]), "+f"(c[3])
                 : "r"(a[0]), "r"(a[1]), "r"(a[2]), "r"(a[3]),
                   "r"(b[0]), "r"(b[1]));
}
__device__ __forceinline__ uint32_t smem_u32(const void* p) {
    uint32_t a;
    asm("{ .reg .u64 t; cvta.to.shared.u64 t, %1; cvt.u32.u64 %0, t; }"
        : "=r"(a) : "l"(p));
    return a;
}
#define CP_ASYNC16(dst, src) \
    asm volatile("cp.async.cg.shared.global [%0], [%1], 16;" \
                 :: "r"(dst), "l"(src) : "memory")
#define CP_COMMIT() asm volatile("cp.async.commit_group;" ::: "memory")
#define CP_WAIT(n)  asm volatile("cp.async.wait_group %0;" :: "n"(n) : "memory")

// ============================================================================
// Pre-kernels: tf32 rounding + sigma-permutation of k-dim columns (DIMC wide)
// ============================================================================
__device__ __forceinline__ void round_perm_body(const float* __restrict__ src,
                                                float* __restrict__ dst) {
    size_t i = ((size_t)blockIdx.x * 256 + threadIdx.x) * 4;
    float4 v = *reinterpret_cast<const float4*>(src + i);
    int col = (int)(i % DIMC);
    size_t rowbase = i - col;
    int cb = (col & ~7) + ((col & 4) ? 1 : 0);
    dst[rowbase + cb]     = tf32f(v.x);
    dst[rowbase + cb + 2] = tf32f(v.y);
    dst[rowbase + cb + 4] = tf32f(v.z);
    dst[rowbase + cb + 6] = tf32f(v.w);
}
__global__ __launch_bounds__(256) void round_x (const float* __restrict__ s) { round_perm_body(s, g_Xr); }
__global__ __launch_bounds__(256) void round_wq(const float* __restrict__ s) { round_perm_body(s, g_Wq); }
__global__ __launch_bounds__(256) void round_wp(const float* __restrict__ s) { round_perm_body(s, g_Wp); }

__global__ __launch_bounds__(256) void presig(const float* __restrict__ m) {
    size_t i = ((size_t)blockIdx.x * 256 + threadIdx.x) * 4;
    float4 v = *reinterpret_cast<const float4*>(m + i);
    float4 o;
    o.x = ATT_SCALE / (1.f + __expf(-v.x));
    o.y = ATT_SCALE / (1.f + __expf(-v.y));
    o.z = ATT_SCALE / (1.f + __expf(-v.z));
    o.w = ATT_SCALE / (1.f + __expf(-v.w));
    *reinterpret_cast<float4*>(g_Msig + i) = o;
}

// ============================================================================
// NT GEMM core v3 (unchanged from R9): cp.async 2-stage, LDS.64 frag loads
// ============================================================================
#define LDK 40

template <int BN, int NC, int MF, int NF, int WMDIV>
__device__ __forceinline__ void gemm_core(const float* __restrict__ A, int lda,
                                          const float* __restrict__ B, int ldb,
                                          float (&acc)[MF][NF][4],
                                          float* smem) {
    float* As[2] = { smem, smem + 128 * LDK };
    float* Bs[2] = { smem + 2 * 128 * LDK, smem + 2 * 128 * LDK + BN * LDK };

    const int tid  = threadIdx.x;
    const int lane = tid & 31;
    const int wid  = tid >> 5;
    const int wm   = wid % WMDIV;
    const int wn   = wid / WMDIV;
    const int mrow0 = wm * (MF * 16);
    const int ncol0 = wn * (NF * 8);
    const int r = lane >> 2, q = lane & 3;

#pragma unroll
    for (int mf = 0; mf < MF; mf++)
#pragma unroll
        for (int nf = 0; nf < NF; nf++)
#pragma unroll
            for (int i = 0; i < 4; i++) acc[mf][nf][i] = 0.f;

    const int arow = tid >> 3, ac = (tid & 7) * 4;

    auto copy = [&](int i, int buf) {
        int k0 = i * 32;
#pragma unroll
        for (int p = 0; p < 4; p++) {
            int row = arow + p * 32;
            CP_ASYNC16(smem_u32(&As[buf][row * LDK + ac]),
                       A + (size_t)row * lda + k0 + ac);
        }
#pragma unroll
        for (int p = 0; p < BN / 32; p++) {
            int row = arow + p * 32;
            CP_ASYNC16(smem_u32(&Bs[buf][row * LDK + ac]),
                       B + (size_t)row * ldb + k0 + ac);
        }
    };

    copy(0, 0); CP_COMMIT();
    copy(1, 1); CP_COMMIT();
    CP_WAIT(1);
    __syncthreads();

#pragma unroll 1
    for (int i = 0; i < NC; i++) {
        const int buf = i & 1;
        const float* Ab = As[buf];
        const float* Bb = Bs[buf];
#pragma unroll
        for (int kk = 0; kk < 32; kk += 8) {
            uint32_t af[MF][4], bf[NF][2];
#pragma unroll
            for (int mf = 0; mf < MF; mf++) {
                float2 a0 = *reinterpret_cast<const float2*>(
                    &Ab[(mrow0 + mf * 16 + r) * LDK + kk + 2 * q]);
                float2 a1 = *reinterpret_cast<const float2*>(
                    &Ab[(mrow0 + mf * 16 + r + 8) * LDK + kk + 2 * q]);
                af[mf][0] = __float_as_uint(a0.x);
                af[mf][1] = __float_as_uint(a1.x);
                af[mf][2] = __float_as_uint(a0.y);
                af[mf][3] = __float_as_uint(a1.y);
            }
#pragma unroll
            for (int nf = 0; nf < NF; nf++) {
                float2 b0 = *reinterpret_cast<const float2*>(
                    &Bb[(ncol0 + nf * 8 + r) * LDK + kk + 2 * q]);
                bf[nf][0] = __float_as_uint(b0.x);
                bf[nf][1] = __float_as_uint(b0.y);
            }
#pragma unroll
            for (int mf = 0; mf < MF; mf++)
#pragma unroll
                for (int nf = 0; nf < NF; nf++)
                    mma_tf32(acc[mf][nf], af[mf], bf[nf]);
        }
        if (i == NC - 1) break;
        __syncthreads();
        if (i + 2 < NC) { copy(i + 2, buf); CP_COMMIT(); CP_WAIT(1); }
        else            { CP_WAIT(0); }
        __syncthreads();
    }
}

// ============================================================================
// Kernel 1: QKV projection + scatter (unchanged from R9)
// ============================================================================
__global__ __launch_bounds__(256) void qkv_tc() {
    extern __shared__ float smf[];
    float acc[4][4][4];
    int brow = blockIdx.y * 128, bcol = blockIdx.x * 128;
    gemm_core<128, 24, 4, 4, 2>(g_Xr + (size_t)brow * DIMC, DIMC,
                                g_Wq + (size_t)bcol * DIMC, DIMC, acc, smf);
    int lane = threadIdx.x & 31, wid = threadIdx.x >> 5;
    int wm = wid % 2, wn = wid / 2, r = lane >> 2, q = lane & 3;
    int part = bcol / 768, rem0 = bcol - part * 768;
    int j0 = 2 * q;
    int s0 = sig8(j0), s1 = sig8(j0 + 1);

#pragma unroll
    for (int mf = 0; mf < 4; mf++)
#pragma unroll
        for (int nf = 0; nf < 4; nf++) {
            int col = rem0 + wn * 32 + nf * 8 + j0;
            int h = col >> 6, d = col & 63;
            int dbase = d - j0;
#pragma unroll
            for (int rr = 0; rr < 2; rr++) {
                int m = brow + wm * 64 + mf * 16 + r + rr * 8;
                int b = m >> 10, nq = m & 1023;
                float v0 = tf32f(acc[mf][nf][rr * 2 + 0]);
                float v1 = tf32f(acc[mf][nf][rr * 2 + 1]);
                if (part < 2) {
                    float* dst = (part == 0) ? g_Q : g_K;
                    size_t base = (((size_t)(b * NHEADS + h)) * SEQ + nq) * HDIM;
                    dst[base + dbase + s0] = v0;
                    dst[base + dbase + s1] = v1;
                } else {
                    size_t pb = ((size_t)(b * NHEADS + h)) * HDIM;
                    g_Vt[(pb + d)     * SEQ + nq] = v0;
                    g_Vt[(pb + d + 1) * SEQ + nq] = v1;
                }
            }
        }
}

// ============================================================================
// Kernel 2: FUSED flash attention, group-streamed softmax (NO max tracking —
// scores are ~N(0,1)-scale, |s| << 88, so exp is safe in fp32).
// Per key-group g: S-mma (4-reg acc) -> gate -> exp -> PV-mma immediately.
// Live regs: qa(32) + od(32) + sacc(4) + temps  ->  no spills at 2 CTAs/SM.
// 3-stage cp.async KV ring, 1 syncthreads per iteration.
// ============================================================================
#define KT 64
#define LDT 72
#define NITER (SEQ / KT)
#define STAGE_F (2 * 64 * LDT)

__global__ __launch_bounds__(256, 2) void flash_tc() {
    extern __shared__ float sm[];

    const int tid = threadIdx.x, lane = tid & 31, wid = tid >> 5;
    const int r = lane >> 2, q = lane & 3;
    const int pair = blockIdx.y;
    const int h = pair % NHEADS, b = pair / NHEADS;
    const int q0 = blockIdx.x * 128;

    const float* Qg = g_Q  + (size_t)pair * SEQ * HDIM;
    const float* Kg = g_K  + (size_t)pair * SEQ * HDIM;
    const float* Vg = g_Vt + (size_t)pair * HDIM * SEQ;
    const float* Mg = g_Msig + (size_t)h * SEQ * SEQ;

    const int crow = tid >> 4, cc = (tid & 15) * 4;

    auto copyKV = [&](int kb, int buf) {
        float* Kd = sm + buf * STAGE_F;
        float* Vd = Kd + 64 * LDT;
        const float* Ksrc = Kg + (size_t)(kb * KT) * HDIM;
        const float* Vsrc = Vg + kb * KT;
#pragma unroll
        for (int p = 0; p < 4; p++) {
            int row = crow + p * 16;
            CP_ASYNC16(smem_u32(&Kd[row * LDT + cc]), Ksrc + (size_t)row * HDIM + cc);
            CP_ASYNC16(smem_u32(&Vd[row * LDT + cc]), Vsrc + (size_t)row * SEQ + cc);
        }
    };

    copyKV(0, 0); CP_COMMIT();
    copyKV(1, 1); CP_COMMIT();

    // ---- Q fragments directly from permuted global ----
    uint32_t qa[8][4];
    {
        const float* qr0 = Qg + (size_t)(q0 + wid * 16 + r) * HDIM;
        const float* qr1 = qr0 + 8 * HDIM;
#pragma unroll
        for (int kk = 0; kk < 8; kk++) {
            float2 v0 = *reinterpret_cast<const float2*>(qr0 + kk * 8 + 2 * q);
            float2 v1 = *reinterpret_cast<const float2*>(qr1 + kk * 8 + 2 * q);
            qa[kk][0] = __float_as_uint(v0.x);
            qa[kk][1] = __float_as_uint(v1.x);
            qa[kk][2] = __float_as_uint(v0.y);
            qa[kk][3] = __float_as_uint(v1.y);
        }
    }

    float od[8][4];
#pragma unroll
    for (int nf = 0; nf < 8; nf++)
#pragma unroll
        for (int i = 0; i < 4; i++) od[nf][i] = 0.f;
    float l0 = 0.f, l1 = 0.f;

    const int row_s0 = q0 + wid * 16 + r;
    const float* Mrow0 = Mg + (size_t)row_s0 * SEQ + 2 * q;
    const float* Mrow1 = Mrow0 + 8 * SEQ;

#pragma unroll 1
    for (int kb = 0; kb < NITER; kb++) {
        if (kb == NITER - 1) { CP_WAIT(0); } else { CP_WAIT(1); }
        __syncthreads();                 // stage kb visible; compute kb-1 done
        if (kb + 2 < NITER) {
            copyKV(kb + 2, (kb + 2) % 3);
            CP_COMMIT();
        }

        const float* Ks = sm + (kb % 3) * STAGE_F;
        const float* Vs = Ks + 64 * LDT;

        // ---- stream key-groups: S (4-reg) -> gate -> exp -> PV ----
#pragma unroll
        for (int g = 0; g < 8; g++) {
            float sacc[4] = {0.f, 0.f, 0.f, 0.f};
            const float* Kr = &Ks[(g * 8 + r) * LDT + 2 * q];
#pragma unroll
            for (int kk = 0; kk < 8; kk++) {
                float2 bv = *reinterpret_cast<const float2*>(Kr + kk * 8);
                uint32_t bf[2] = { __float_as_uint(bv.x), __float_as_uint(bv.y) };
                mma_tf32(sacc, qa[kk], bf);
            }

            int col = kb * KT + g * 8;
            float2 g0 = *reinterpret_cast<const float2*>(Mrow0 + col);
            float2 g1 = *reinterpret_cast<const float2*>(Mrow1 + col);
            float p00 = __expf(sacc[0] * g0.x);
            float p01 = __expf(sacc[1] * g0.y);
            float p10 = __expf(sacc[2] * g1.x);
            float p11 = __expf(sacc[3] * g1.y);
            l0 += p00 + p01; l1 += p10 + p11;

            uint32_t af[4] = { cvt_tf32(p00), cvt_tf32(p10),
                               cvt_tf32(p01), cvt_tf32(p11) };
            const float* Vr = &Vs[r * LDT + g * 8 + 2 * q];
#pragma unroll
            for (int nf = 0; nf < 8; nf++) {
                float2 bv = *reinterpret_cast<const float2*>(Vr + nf * 8 * LDT);
                uint32_t bf[2] = { __float_as_uint(bv.x), __float_as_uint(bv.y) };
                mma_tf32(od[nf], af, bf);
            }
        }
    }

    // ---- normalize and write O (tf32-rounded, k-sigma-permuted for proj) ----
    l0 += __shfl_xor_sync(0xffffffffu, l0, 1);
    l0 += __shfl_xor_sync(0xffffffffu, l0, 2);
    l1 += __shfl_xor_sync(0xffffffffu, l1, 1);
    l1 += __shfl_xor_sync(0xffffffffu, l1, 2);
    float inv0 = 1.f / l0, inv1 = 1.f / l1;

    size_t orow0 = (size_t)b * SEQ + q0 + wid * 16 + r;
    int j0 = 2 * q;
    int s0 = sig8(j0), s1 = sig8(j0 + 1);
#pragma unroll
    for (int nf = 0; nf < 8; nf++) {
        int cbase = h * HDIM + nf * 8;
        g_O[orow0 * DIMC + cbase + s0]       = tf32f(od[nf][0] * inv0);
        g_O[orow0 * DIMC + cbase + s1]       = tf32f(od[nf][1] * inv0);
        g_O[(orow0 + 8) * DIMC + cbase + s0] = tf32f(od[nf][2] * inv1);
        g_O[(orow0 + 8) * DIMC + cbase + s1] = tf32f(od[nf][3] * inv1);
    }
}

// ============================================================================
// Kernel 3: out = O @ Wproj^T + bias (unchanged from R9)
// ============================================================================
__global__ __launch_bounds__(256) void proj_tc(const float* __restrict__ bias,
                                               float* __restrict__ out) {
    extern __shared__ float smf[];
    float acc[4][4][4];
    int brow = blockIdx.y * 128, bcol = blockIdx.x * 128;
    gemm_core<128, 24, 4, 4, 2>(g_O + (size_t)brow * DIMC, DIMC,
                                g_Wp + (size_t)bcol * DIMC, DIMC, acc, smf);
    int lane = threadIdx.x & 31, wid = threadIdx.x >> 5;
    int wm = wid % 2, wn = wid / 2, r = lane >> 2, q = lane & 3;

#pragma unroll
    for (int mf = 0; mf < 4; mf++)
#pragma unroll
        for (int nf = 0; nf < 4; nf++) {
            int col = bcol + wn * 32 + nf * 8 + q * 2;
            float2 bb = *reinterpret_cast<const float2*>(&bias[col]);
#pragma unroll
            for (int rr = 0; rr < 2; rr++) {
                int row = brow + wm * 64 + mf * 16 + r + rr * 8;
                float v0 = acc[mf][nf][rr * 2 + 0] + bb.x;
                float v1 = acc[mf][nf][rr * 2 + 1] + bb.y;
                *reinterpret_cast<float2*>(&out[(size_t)row * DIMC + col]) = make_float2(v0, v1);
            }
        }
}

// ============================================================================
extern "C" void kernel_launch(void* const* d_in, const int* in_sizes, int n_in,
                              void* d_out, int out_size) {
    (void)in_sizes; (void)n_in; (void)out_size;
    const float* x        = (const float*)d_in[0];
    const float* w_qkv    = (const float*)d_in[1];
    const float* w_proj   = (const float*)d_in[2];
    const float* b_proj   = (const float*)d_in[3];
    const float* att_mask = (const float*)d_in[4];
    float* out = (float*)d_out;

    const int GEMM_SMEM  = (4 * 128 * LDK) * (int)sizeof(float);   // 81920
    const int FLASH_SMEM = (3 * STAGE_F) * (int)sizeof(float);     // 110592

    cudaFuncSetAttribute(qkv_tc,   cudaFuncAttributeMaxDynamicSharedMemorySize, GEMM_SMEM);
    cudaFuncSetAttribute(proj_tc,  cudaFuncAttributeMaxDynamicSharedMemorySize, GEMM_SMEM);
    cudaFuncSetAttribute(flash_tc, cudaFuncAttributeMaxDynamicSharedMemorySize, FLASH_SMEM);

    round_x <<<(MROWS * DIMC) / 1024, 256>>>(x);
    round_wq<<<(3 * DIMC * DIMC) / 1024, 256>>>(w_qkv);
    round_wp<<<(DIMC * DIMC) / 1024, 256>>>(w_proj);
    presig  <<<(NHEADS * SEQ * SEQ) / 1024, 256>>>(att_mask);

    qkv_tc  <<<dim3(2304 / 128, MROWS / 128), 256, GEMM_SMEM>>>();
    flash_tc<<<dim3(SEQ / 128, PAIRS), 256, FLASH_SMEM>>>();
    proj_tc <<<dim3(DIMC / 128, MROWS / 128), 256, GEMM_SMEM>>>(b_proj, out);
}

// round 11
// speedup vs baseline: 1.5695x; 1.0076x over previous
#include <cuda_runtime.h>
#include <cstdint>
#include <math.h>

#define DIMC   768
#define NHEADS 12
#define HDIM   64
#define BATCH  8
#define SEQ    1024
#define MROWS  (BATCH*SEQ)
#define PAIRS  (BATCH*NHEADS)
#define ATT_SCALE 0.125f

// ---------------- scratch (static device memory; no cudaMalloc allowed) ----
__device__ __align__(16) float g_Q   [(size_t)PAIRS*SEQ*HDIM];
__device__ __align__(16) float g_K   [(size_t)PAIRS*SEQ*HDIM];
__device__ __align__(16) float g_Vt  [(size_t)PAIRS*HDIM*SEQ];
__device__ __align__(16) float g_O   [(size_t)MROWS*DIMC];
__device__ __align__(16) float g_Msig[(size_t)NHEADS*SEQ*SEQ];
__device__ __align__(16) float g_Xr  [(size_t)MROWS*DIMC];
__device__ __align__(16) float g_Wq  [(size_t)3*DIMC*DIMC];
__device__ __align__(16) float g_Wp  [(size_t)DIMC*DIMC];

// ======================= helpers ===========================================
__device__ __forceinline__ uint32_t cvt_tf32(float x) {
    uint32_t r; asm("cvt.rna.tf32.f32 %0, %1;" : "=r"(r) : "f"(x)); return r;
}
__device__ __forceinline__ float tf32f(float x) {
    return __uint_as_float(cvt_tf32(x));
}
__device__ __forceinline__ int sig8(int j) {           // 0,2,4,6,1,3,5,7
    return ((j & 3) << 1) | (j >> 2);
}
__device__ __forceinline__ void mma_tf32(float (&c)[4], const uint32_t (&a)[4],
                                         const uint32_t (&b)[2]) {
    asm volatile("mma.sync.aligned.m16n8k8.row.col.f32.tf32.tf32.f32 "
                 "{%0,%1,%2,%3}, {%4,%5,%6,%7}, {%8,%9}, {%0,%1,%2,%3};"
                 : "+f"(c[0]), "+f"(c[1]), "+f"(c[2]), "+f"(c[3])
                 : "r"(a[0]), "r"(a[1]), "r"(a[2]), "r"(a[3]),
                   "r"(b[0]), "r"(b[1]));
}
__device__ __forceinline__ uint32_t smem_u32(const void* p) {
    uint32_t a;
    asm("{ .reg .u64 t; cvta.to.shared.u64 t, %1; cvt.u32.u64 %0, t; }"
        : "=r"(a) : "l"(p));
    return a;
}
#define CP_ASYNC16(dst, src) \
    asm volatile("cp.async.cg.shared.global [%0], [%1], 16;" \
                 :: "r"(dst), "l"(src) : "memory")
#define CP_COMMIT() asm volatile("cp.async.commit_group;" ::: "memory")
#define CP_WAIT(n)  asm volatile("cp.async.wait_group %0;" :: "n"(n) : "memory")

// ============================================================================
// Pre-kernels: one fused tf32 round+sigma-permute over x|w_qkv|w_proj, + presig
// ============================================================================
#define NB_X  (MROWS * DIMC / 1024)          // 6144
#define NB_WQ (3 * DIMC * DIMC / 1024)       // 1728
#define NB_WP (DIMC * DIMC / 1024)           // 576

__device__ __forceinline__ void round_perm_elem(const float* __restrict__ src,
                                                float* __restrict__ dst,
                                                size_t i) {
    float4 v = *reinterpret_cast<const float4*>(src + i);
    int col = (int)(i % DIMC);
    size_t rowbase = i - col;
    int cb = (col & ~7) + ((col & 4) ? 1 : 0);
    dst[rowbase + cb]     = tf32f(v.x);
    dst[rowbase + cb + 2] = tf32f(v.y);
    dst[rowbase + cb + 4] = tf32f(v.z);
    dst[rowbase + cb + 6] = tf32f(v.w);
}

__global__ __launch_bounds__(256) void round_all(const float* __restrict__ x,
                                                 const float* __restrict__ wq,
                                                 const float* __restrict__ wp) {
    int blk = blockIdx.x;
    if (blk < NB_X) {
        size_t i = ((size_t)blk * 256 + threadIdx.x) * 4;
        round_perm_elem(x, g_Xr, i);
    } else if (blk < NB_X + NB_WQ) {
        size_t i = ((size_t)(blk - NB_X) * 256 + threadIdx.x) * 4;
        round_perm_elem(wq, g_Wq, i);
    } else {
        size_t i = ((size_t)(blk - NB_X - NB_WQ) * 256 + threadIdx.x) * 4;
        round_perm_elem(wp, g_Wp, i);
    }
}

__global__ __launch_bounds__(256) void presig(const float* __restrict__ m) {
    size_t i = ((size_t)blockIdx.x * 256 + threadIdx.x) * 4;
    float4 v = *reinterpret_cast<const float4*>(m + i);
    float4 o;
    o.x = ATT_SCALE / (1.f + __expf(-v.x));
    o.y = ATT_SCALE / (1.f + __expf(-v.y));
    o.z = ATT_SCALE / (1.f + __expf(-v.z));
    o.w = ATT_SCALE / (1.f + __expf(-v.w));
    *reinterpret_cast<float4*>(g_Msig + i) = o;
}

// ============================================================================
// NT GEMM core v3 (unchanged): cp.async 2-stage, LDS.64 frag loads
// ============================================================================
#define LDK 40

template <int BN, int NC, int MF, int NF, int WMDIV>
__device__ __forceinline__ void gemm_core(const float* __restrict__ A, int lda,
                                          const float* __restrict__ B, int ldb,
                                          float (&acc)[MF][NF][4],
                                          float* smem) {
    float* As[2] = { smem, smem + 128 * LDK };
    float* Bs[2] = { smem + 2 * 128 * LDK, smem + 2 * 128 * LDK + BN * LDK };

    const int tid  = threadIdx.x;
    const int lane = tid & 31;
    const int wid  = tid >> 5;
    const int wm   = wid % WMDIV;
    const int wn   = wid / WMDIV;
    const int mrow0 = wm * (MF * 16);
    const int ncol0 = wn * (NF * 8);
    const int r = lane >> 2, q = lane & 3;

#pragma unroll
    for (int mf = 0; mf < MF; mf++)
#pragma unroll
        for (int nf = 0; nf < NF; nf++)
#pragma unroll
            for (int i = 0; i < 4; i++) acc[mf][nf][i] = 0.f;

    const int arow = tid >> 3, ac = (tid & 7) * 4;

    auto copy = [&](int i, int buf) {
        int k0 = i * 32;
#pragma unroll
        for (int p = 0; p < 4; p++) {
            int row = arow + p * 32;
            CP_ASYNC16(smem_u32(&As[buf][row * LDK + ac]),
                       A + (size_t)row * lda + k0 + ac);
        }
#pragma unroll
        for (int p = 0; p < BN / 32; p++) {
            int row = arow + p * 32;
            CP_ASYNC16(smem_u32(&Bs[buf][row * LDK + ac]),
                       B + (size_t)row * ldb + k0 + ac);
        }
    };

    copy(0, 0); CP_COMMIT();
    copy(1, 1); CP_COMMIT();
    CP_WAIT(1);
    __syncthreads();

#pragma unroll 1
    for (int i = 0; i < NC; i++) {
        const int buf = i & 1;
        const float* Ab = As[buf];
        const float* Bb = Bs[buf];
#pragma unroll
        for (int kk = 0; kk < 32; kk += 8) {
            uint32_t af[MF][4], bf[NF][2];
#pragma unroll
            for (int mf = 0; mf < MF; mf++) {
                float2 a0 = *reinterpret_cast<const float2*>(
                    &Ab[(mrow0 + mf * 16 + r) * LDK + kk + 2 * q]);
                float2 a1 = *reinterpret_cast<const float2*>(
                    &Ab[(mrow0 + mf * 16 + r + 8) * LDK + kk + 2 * q]);
                af[mf][0] = __float_as_uint(a0.x);
                af[mf][1] = __float_as_uint(a1.x);
                af[mf][2] = __float_as_uint(a0.y);
                af[mf][3] = __float_as_uint(a1.y);
            }
#pragma unroll
            for (int nf = 0; nf < NF; nf++) {
                float2 b0 = *reinterpret_cast<const float2*>(
                    &Bb[(ncol0 + nf * 8 + r) * LDK + kk + 2 * q]);
                bf[nf][0] = __float_as_uint(b0.x);
                bf[nf][1] = __float_as_uint(b0.y);
            }
#pragma unroll
            for (int mf = 0; mf < MF; mf++)
#pragma unroll
                for (int nf = 0; nf < NF; nf++)
                    mma_tf32(acc[mf][nf], af[mf], bf[nf]);
        }
        if (i == NC - 1) break;
        __syncthreads();
        if (i + 2 < NC) { copy(i + 2, buf); CP_COMMIT(); CP_WAIT(1); }
        else            { CP_WAIT(0); }
        __syncthreads();
    }
}

// ============================================================================
// Kernel 1: QKV projection + scatter (unchanged)
// ============================================================================
__global__ __launch_bounds__(256) void qkv_tc() {
    extern __shared__ float smf[];
    float acc[4][4][4];
    int brow = blockIdx.y * 128, bcol = blockIdx.x * 128;
    gemm_core<128, 24, 4, 4, 2>(g_Xr + (size_t)brow * DIMC, DIMC,
                                g_Wq + (size_t)bcol * DIMC, DIMC, acc, smf);
    int lane = threadIdx.x & 31, wid = threadIdx.x >> 5;
    int wm = wid % 2, wn = wid / 2, r = lane >> 2, q = lane & 3;
    int part = bcol / 768, rem0 = bcol - part * 768;
    int j0 = 2 * q;
    int s0 = sig8(j0), s1 = sig8(j0 + 1);

#pragma unroll
    for (int mf = 0; mf < 4; mf++)
#pragma unroll
        for (int nf = 0; nf < 4; nf++) {
            int col = rem0 + wn * 32 + nf * 8 + j0;
            int h = col >> 6, d = col & 63;
            int dbase = d - j0;
#pragma unroll
            for (int rr = 0; rr < 2; rr++) {
                int m = brow + wm * 64 + mf * 16 + r + rr * 8;
                int b = m >> 10, nq = m & 1023;
                float v0 = tf32f(acc[mf][nf][rr * 2 + 0]);
                float v1 = tf32f(acc[mf][nf][rr * 2 + 1]);
                if (part < 2) {
                    float* dst = (part == 0) ? g_Q : g_K;
                    size_t base = (((size_t)(b * NHEADS + h)) * SEQ + nq) * HDIM;
                    dst[base + dbase + s0] = v0;
                    dst[base + dbase + s1] = v1;
                } else {
                    size_t pb = ((size_t)(b * NHEADS + h)) * HDIM;
                    g_Vt[(pb + d)     * SEQ + nq] = v0;
                    g_Vt[(pb + d + 1) * SEQ + nq] = v1;
                }
            }
        }
}

// ============================================================================
// Kernel 2: FUSED flash attention.
//  - grid (pair, q-tile): concurrent wave spans all pairs -> 8-way L2 reuse
//    of each head's mask slice (18 MB working set, L2-resident)
//  - S-MMA chain split into 2 parallel accumulators (2x tensor ILP)
//  - group-streamed no-max softmax, P in registers, 3-stage cp.async ring
// ============================================================================
#define KT 64
#define LDT 72
#define NITER (SEQ / KT)
#define STAGE_F (2 * 64 * LDT)

__global__ __launch_bounds__(256, 2) void flash_tc() {
    extern __shared__ float sm[];

    const int tid = threadIdx.x, lane = tid & 31, wid = tid >> 5;
    const int r = lane >> 2, q = lane & 3;
    const int pair = blockIdx.x;                 // pair fastest -> mask L2 reuse
    const int h = pair % NHEADS, b = pair / NHEADS;
    const int q0 = blockIdx.y * 128;

    const float* Qg = g_Q  + (size_t)pair * SEQ * HDIM;
    const float* Kg = g_K  + (size_t)pair * SEQ * HDIM;
    const float* Vg = g_Vt + (size_t)pair * HDIM * SEQ;
    const float* Mg = g_Msig + (size_t)h * SEQ * SEQ;

    const int crow = tid >> 4, cc = (tid & 15) * 4;

    auto copyKV = [&](int kb, int buf) {
        float* Kd = sm + buf * STAGE_F;
        float* Vd = Kd + 64 * LDT;
        const float* Ksrc = Kg + (size_t)(kb * KT) * HDIM;
        const float* Vsrc = Vg + kb * KT;
#pragma unroll
        for (int p = 0; p < 4; p++) {
            int row = crow + p * 16;
            CP_ASYNC16(smem_u32(&Kd[row * LDT + cc]), Ksrc + (size_t)row * HDIM + cc);
            CP_ASYNC16(smem_u32(&Vd[row * LDT + cc]), Vsrc + (size_t)row * SEQ + cc);
        }
    };

    copyKV(0, 0); CP_COMMIT();
    copyKV(1, 1); CP_COMMIT();

    // ---- Q fragments directly from permuted global ----
    uint32_t qa[8][4];
    {
        const float* qr0 = Qg + (size_t)(q0 + wid * 16 + r) * HDIM;
        const float* qr1 = qr0 + 8 * HDIM;
#pragma unroll
        for (int kk = 0; kk < 8; kk++) {
            float2 v0 = *reinterpret_cast<const float2*>(qr0 + kk * 8 + 2 * q);
            float2 v1 = *reinterpret_cast<const float2*>(qr1 + kk * 8 + 2 * q);
            qa[kk][0] = __float_as_uint(v0.x);
            qa[kk][1] = __float_as_uint(v1.x);
            qa[kk][2] = __float_as_uint(v0.y);
            qa[kk][3] = __float_as_uint(v1.y);
        }
    }

    float od[8][4];
#pragma unroll
    for (int nf = 0; nf < 8; nf++)
#pragma unroll
        for (int i = 0; i < 4; i++) od[nf][i] = 0.f;
    float l0 = 0.f, l1 = 0.f;

    const int row_s0 = q0 + wid * 16 + r;
    const float* Mrow0 = Mg + (size_t)row_s0 * SEQ + 2 * q;
    const float* Mrow1 = Mrow0 + 8 * SEQ;

#pragma unroll 1
    for (int kb = 0; kb < NITER; kb++) {
        if (kb == NITER - 1) { CP_WAIT(0); } else { CP_WAIT(1); }
        __syncthreads();
        if (kb + 2 < NITER) {
            copyKV(kb + 2, (kb + 2) % 3);
            CP_COMMIT();
        }

        const float* Ks = sm + (kb % 3) * STAGE_F;
        const float* Vs = Ks + 64 * LDT;

        // ---- stream key-groups: S (2 parallel chains) -> gate/exp -> PV ----
#pragma unroll
        for (int g = 0; g < 8; g++) {
            float sa[4] = {0.f, 0.f, 0.f, 0.f};
            float sb[4] = {0.f, 0.f, 0.f, 0.f};
            const float* Kr = &Ks[(g * 8 + r) * LDT + 2 * q];
#pragma unroll
            for (int kk = 0; kk < 8; kk += 2) {
                float2 b0 = *reinterpret_cast<const float2*>(Kr + kk * 8);
                float2 b1 = *reinterpret_cast<const float2*>(Kr + (kk + 1) * 8);
                uint32_t bf0[2] = { __float_as_uint(b0.x), __float_as_uint(b0.y) };
                uint32_t bf1[2] = { __float_as_uint(b1.x), __float_as_uint(b1.y) };
                mma_tf32(sa, qa[kk],     bf0);
                mma_tf32(sb, qa[kk + 1], bf1);
            }
            sa[0] += sb[0]; sa[1] += sb[1]; sa[2] += sb[2]; sa[3] += sb[3];

            int col = kb * KT + g * 8;
            float2 g0 = *reinterpret_cast<const float2*>(Mrow0 + col);
            float2 g1 = *reinterpret_cast<const float2*>(Mrow1 + col);
            float p00 = __expf(sa[0] * g0.x);
            float p01 = __expf(sa[1] * g0.y);
            float p10 = __expf(sa[2] * g1.x);
            float p11 = __expf(sa[3] * g1.y);
            l0 += p00 + p01; l1 += p10 + p11;

            uint32_t af[4] = { cvt_tf32(p00), cvt_tf32(p10),
                               cvt_tf32(p01), cvt_tf32(p11) };
            const float* Vr = &Vs[r * LDT + g * 8 + 2 * q];
#pragma unroll
            for (int nf = 0; nf < 8; nf++) {
                float2 bv = *reinterpret_cast<const float2*>(Vr + nf * 8 * LDT);
                uint32_t bf[2] = { __float_as_uint(bv.x), __float_as_uint(bv.y) };
                mma_tf32(od[nf], af, bf);
            }
        }
    }

    // ---- normalize and write O ----
    l0 += __shfl_xor_sync(0xffffffffu, l0, 1);
    l0 += __shfl_xor_sync(0xffffffffu, l0, 2);
    l1 += __shfl_xor_sync(0xffffffffu, l1, 1);
    l1 += __shfl_xor_sync(0xffffffffu, l1, 2);
    float inv0 = 1.f / l0, inv1 = 1.f / l1;

    size_t orow0 = (size_t)b * SEQ + q0 + wid * 16 + r;
    int j0 = 2 * q;
    int s0 = sig8(j0), s1 = sig8(j0 + 1);
#pragma unroll
    for (int nf = 0; nf < 8; nf++) {
        int cbase = h * HDIM + nf * 8;
        g_O[orow0 * DIMC + cbase + s0]       = tf32f(od[nf][0] * inv0);
        g_O[orow0 * DIMC + cbase + s1]       = tf32f(od[nf][1] * inv0);
        g_O[(orow0 + 8) * DIMC + cbase + s0] = tf32f(od[nf][2] * inv1);
        g_O[(orow0 + 8) * DIMC + cbase + s1] = tf32f(od[nf][3] * inv1);
    }
}

// ============================================================================
// Kernel 3: out = O @ Wproj^T + bias (unchanged)
// ============================================================================
__global__ __launch_bounds__(256) void proj_tc(const float* __restrict__ bias,
                                               float* __restrict__ out) {
    extern __shared__ float smf[];
    float acc[4][4][4];
    int brow = blockIdx.y * 128, bcol = blockIdx.x * 128;
    gemm_core<128, 24, 4, 4, 2>(g_O + (size_t)brow * DIMC, DIMC,
                                g_Wp + (size_t)bcol * DIMC, DIMC, acc, smf);
    int lane = threadIdx.x & 31, wid = threadIdx.x >> 5;
    int wm = wid % 2, wn = wid / 2, r = lane >> 2, q = lane & 3;

#pragma unroll
    for (int mf = 0; mf < 4; mf++)
#pragma unroll
        for (int nf = 0; nf < 4; nf++) {
            int col = bcol + wn * 32 + nf * 8 + q * 2;
            float2 bb = *reinterpret_cast<const float2*>(&bias[col]);
#pragma unroll
            for (int rr = 0; rr < 2; rr++) {
                int row = brow + wm * 64 + mf * 16 + r + rr * 8;
                float v0 = acc[mf][nf][rr * 2 + 0] + bb.x;
                float v1 = acc[mf][nf][rr * 2 + 1] + bb.y;
                *reinterpret_cast<float2*>(&out[(size_t)row * DIMC + col]) = make_float2(v0, v1);
            }
        }
}

// ============================================================================
extern "C" void kernel_launch(void* const* d_in, const int* in_sizes, int n_in,
                              void* d_out, int out_size) {
    (void)in_sizes; (void)n_in; (void)out_size;
    const float* x        = (const float*)d_in[0];
    const float* w_qkv    = (const float*)d_in[1];
    const float* w_proj   = (const float*)d_in[2];
    const float* b_proj   = (const float*)d_in[3];
    const float* att_mask = (const float*)d_in[4];
    float* out = (float*)d_out;

    const int GEMM_SMEM  = (4 * 128 * LDK) * (int)sizeof(float);   // 81920
    const int FLASH_SMEM = (3 * STAGE_F) * (int)sizeof(float);     // 110592

    cudaFuncSetAttribute(qkv_tc,   cudaFuncAttributeMaxDynamicSharedMemorySize, GEMM_SMEM);
    cudaFuncSetAttribute(proj_tc,  cudaFuncAttributeMaxDynamicSharedMemorySize, GEMM_SMEM);
    cudaFuncSetAttribute(flash_tc, cudaFuncAttributeMaxDynamicSharedMemorySize, FLASH_SMEM);

    round_all<<<NB_X + NB_WQ + NB_WP, 256>>>(x, w_qkv, w_proj);
    presig   <<<(NHEADS * SEQ * SEQ) / 1024, 256>>>(att_mask);

    qkv_tc  <<<dim3(2304 / 128, MROWS / 128), 256, GEMM_SMEM>>>();
    flash_tc<<<dim3(PAIRS, SEQ / 128), 256, FLASH_SMEM>>>();
    proj_tc <<<dim3(DIMC / 128, MROWS / 128), 256, GEMM_SMEM>>>(b_proj, out);
}

// round 12
// speedup vs baseline: 1.6097x; 1.0256x over previous
#include <cuda_runtime.h>
#include <cstdint>
#include <math.h>

#define DIMC   768
#define NHEADS 12
#define HDIM   64
#define BATCH  8
#define SEQ    1024
#define MROWS  (BATCH*SEQ)
#define PAIRS  (BATCH*NHEADS)
#define ATT_SCALE 0.125f

// ---------------- scratch (static device memory; no cudaMalloc allowed) ----
// sigma16 k-permutation: logical k j stored at (j&~15) + (j&3)*4 + ((j>>3)&1)*2 + ((j&7)>>2)
// g_Q/g_K : tf32, d-dim sigma16-permuted.  g_Vt: tf32, plain [pair][d][key].
// g_O     : tf32, DIMC sigma16-permuted.   g_Xr/g_Wq/g_Wp: tf32, k sigma16-permuted.
__device__ __align__(16) float g_Q   [(size_t)PAIRS*SEQ*HDIM];
__device__ __align__(16) float g_K   [(size_t)PAIRS*SEQ*HDIM];
__device__ __align__(16) float g_Vt  [(size_t)PAIRS*HDIM*SEQ];
__device__ __align__(16) float g_O   [(size_t)MROWS*DIMC];
__device__ __align__(16) float g_Msig[(size_t)NHEADS*SEQ*SEQ];
__device__ __align__(16) float g_Xr  [(size_t)MROWS*DIMC];
__device__ __align__(16) float g_Wq  [(size_t)3*DIMC*DIMC];
__device__ __align__(16) float g_Wp  [(size_t)DIMC*DIMC];

// ======================= helpers ===========================================
__device__ __forceinline__ uint32_t cvt_tf32(float x) {
    uint32_t r; asm("cvt.rna.tf32.f32 %0, %1;" : "=r"(r) : "f"(x)); return r;
}
__device__ __forceinline__ float tf32f(float x) {
    return __uint_as_float(cvt_tf32(x));
}
__device__ __forceinline__ int sig16(int j) {
    int jj = j & 15, jjj = jj & 7;
    return (j & ~15) + (jjj & 3) * 4 + (jj >> 3) * 2 + (jjj >> 2);
}
__device__ __forceinline__ void mma_tf32(float (&c)[4], const uint32_t (&a)[4],
                                         const uint32_t (&b)[2]) {
    asm volatile("mma.sync.aligned.m16n8k8.row.col.f32.tf32.tf32.f32 "
                 "{%0,%1,%2,%3}, {%4,%5,%6,%7}, {%8,%9}, {%0,%1,%2,%3};"
                 : "+f"(c[0]), "+f"(c[1]), "+f"(c[2]), "+f"(c[3])
                 : "r"(a[0]), "r"(a[1]), "r"(a[2]), "r"(a[3]),
                   "r"(b[0]), "r"(b[1]));
}
__device__ __forceinline__ uint32_t smem_u32(const void* p) {
    uint32_t a;
    asm("{ .reg .u64 t; cvta.to.shared.u64 t, %1; cvt.u32.u64 %0, t; }"
        : "=r"(a) : "l"(p));
    return a;
}
#define CP_ASYNC16(dst, src) \
    asm volatile("cp.async.cg.shared.global [%0], [%1], 16;" \
                 :: "r"(dst), "l"(src) : "memory")
#define CP_COMMIT() asm volatile("cp.async.commit_group;" ::: "memory")
#define CP_WAIT(n)  asm volatile("cp.async.wait_group %0;" :: "n"(n) : "memory")

// ============================================================================
// Pre-kernels: fused tf32 round + sigma16 permutation; presig
// ============================================================================
#define NB_X  (MROWS * DIMC / 1024)
#define NB_WQ (3 * DIMC * DIMC / 1024)
#define NB_WP (DIMC * DIMC / 1024)

__device__ __forceinline__ void round_perm_elem(const float* __restrict__ src,
                                                float* __restrict__ dst,
                                                size_t i) {
    float4 v = *reinterpret_cast<const float4*>(src + i);
    int col = (int)(i % DIMC);                     // multiple of 4
    size_t rowbase = i - col;
    int off = ((col >> 3) & 1) * 2 + ((col >> 2) & 1);
    size_t d0 = rowbase + (col & ~15) + off;
    dst[d0]      = tf32f(v.x);
    dst[d0 + 4]  = tf32f(v.y);
    dst[d0 + 8]  = tf32f(v.z);
    dst[d0 + 12] = tf32f(v.w);
}

__global__ __launch_bounds__(256) void round_all(const float* __restrict__ x,
                                                 const float* __restrict__ wq,
                                                 const float* __restrict__ wp) {
    int blk = blockIdx.x;
    if (blk < NB_X) {
        round_perm_elem(x, g_Xr, ((size_t)blk * 256 + threadIdx.x) * 4);
    } else if (blk < NB_X + NB_WQ) {
        round_perm_elem(wq, g_Wq, ((size_t)(blk - NB_X) * 256 + threadIdx.x) * 4);
    } else {
        round_perm_elem(wp, g_Wp, ((size_t)(blk - NB_X - NB_WQ) * 256 + threadIdx.x) * 4);
    }
}

__global__ __launch_bounds__(256) void presig(const float* __restrict__ m) {
    size_t i = ((size_t)blockIdx.x * 256 + threadIdx.x) * 4;
    float4 v = *reinterpret_cast<const float4*>(m + i);
    float4 o;
    o.x = ATT_SCALE / (1.f + __expf(-v.x));
    o.y = ATT_SCALE / (1.f + __expf(-v.y));
    o.z = ATT_SCALE / (1.f + __expf(-v.z));
    o.w = ATT_SCALE / (1.f + __expf(-v.w));
    *reinterpret_cast<float4*>(g_Msig + i) = o;
}

// ============================================================================
// NT GEMM core v4: cp.async 2-stage, LDK=48 (16 mod 32), ALL fragment loads
// are conflict-free LDS.128 (operands sigma16-permuted along k).
// ============================================================================
#define LDK 48

template <int BN, int NC, int MF, int NF, int WMDIV>
__device__ __forceinline__ void gemm_core(const float* __restrict__ A, int lda,
                                          const float* __restrict__ B, int ldb,
                                          float (&acc)[MF][NF][4],
                                          float* smem) {
    float* As[2] = { smem, smem + 128 * LDK };
    float* Bs[2] = { smem + 2 * 128 * LDK, smem + 2 * 128 * LDK + BN * LDK };

    const int tid  = threadIdx.x;
    const int lane = tid & 31;
    const int wid  = tid >> 5;
    const int wm   = wid % WMDIV;
    const int wn   = wid / WMDIV;
    const int mrow0 = wm * (MF * 16);
    const int ncol0 = wn * (NF * 8);
    const int r = lane >> 2, q = lane & 3;

#pragma unroll
    for (int mf = 0; mf < MF; mf++)
#pragma unroll
        for (int nf = 0; nf < NF; nf++)
#pragma unroll
            for (int i = 0; i < 4; i++) acc[mf][nf][i] = 0.f;

    const int arow = tid >> 3, ac = (tid & 7) * 4;

    auto copy = [&](int i, int buf) {
        int k0 = i * 32;
#pragma unroll
        for (int p = 0; p < 4; p++) {
            int row = arow + p * 32;
            CP_ASYNC16(smem_u32(&As[buf][row * LDK + ac]),
                       A + (size_t)row * lda + k0 + ac);
        }
#pragma unroll
        for (int p = 0; p < BN / 32; p++) {
            int row = arow + p * 32;
            CP_ASYNC16(smem_u32(&Bs[buf][row * LDK + ac]),
                       B + (size_t)row * ldb + k0 + ac);
        }
    };

    copy(0, 0); CP_COMMIT();
    copy(1, 1); CP_COMMIT();
    CP_WAIT(1);
    __syncthreads();

#pragma unroll 1
    for (int i = 0; i < NC; i++) {
        const int buf = i & 1;
        const float* Ab = As[buf];
        const float* Bb = Bs[buf];
#pragma unroll
        for (int blk = 0; blk < 2; blk++) {         // 2 x (two k-steps)
            uint32_t af[MF][2][4], bf[NF][2][2];
#pragma unroll
            for (int mf = 0; mf < MF; mf++) {
                const float* ap = &Ab[(mrow0 + mf * 16 + r) * LDK + blk * 16 + 4 * q];
                float4 a0 = *reinterpret_cast<const float4*>(ap);
                float4 a1 = *reinterpret_cast<const float4*>(ap + 8 * LDK);
                af[mf][0][0] = __float_as_uint(a0.x); af[mf][0][1] = __float_as_uint(a1.x);
                af[mf][0][2] = __float_as_uint(a0.y); af[mf][0][3] = __float_as_uint(a1.y);
                af[mf][1][0] = __float_as_uint(a0.z); af[mf][1][1] = __float_as_uint(a1.z);
                af[mf][1][2] = __float_as_uint(a0.w); af[mf][1][3] = __float_as_uint(a1.w);
            }
#pragma unroll
            for (int nf = 0; nf < NF; nf++) {
                float4 b = *reinterpret_cast<const float4*>(
                    &Bb[(ncol0 + nf * 8 + r) * LDK + blk * 16 + 4 * q]);
                bf[nf][0][0] = __float_as_uint(b.x); bf[nf][0][1] = __float_as_uint(b.y);
                bf[nf][1][0] = __float_as_uint(b.z); bf[nf][1][1] = __float_as_uint(b.w);
            }
#pragma unroll
            for (int mf = 0; mf < MF; mf++)
#pragma unroll
                for (int nf = 0; nf < NF; nf++) {
                    mma_tf32(acc[mf][nf], af[mf][0], bf[nf][0]);
                    mma_tf32(acc[mf][nf], af[mf][1], bf[nf][1]);
                }
        }
        if (i == NC - 1) break;
        __syncthreads();
        if (i + 2 < NC) { copy(i + 2, buf); CP_COMMIT(); CP_WAIT(1); }
        else            { CP_WAIT(0); }
        __syncthreads();
    }
}

// ============================================================================
// Kernel 1: QKV projection + scatter. Q/K stored d-sigma16; V plain.
// ============================================================================
__global__ __launch_bounds__(256) void qkv_tc() {
    extern __shared__ float smf[];
    float acc[4][4][4];
    int brow = blockIdx.y * 128, bcol = blockIdx.x * 128;
    gemm_core<128, 24, 4, 4, 2>(g_Xr + (size_t)brow * DIMC, DIMC,
                                g_Wq + (size_t)bcol * DIMC, DIMC, acc, smf);
    int lane = threadIdx.x & 31, wid = threadIdx.x >> 5;
    int wm = wid % 2, wn = wid / 2, r = lane >> 2, q = lane & 3;
    int part = bcol / 768, rem0 = bcol - part * 768;

#pragma unroll
    for (int mf = 0; mf < 4; mf++)
#pragma unroll
        for (int nf = 0; nf < 4; nf++) {
            int col = rem0 + wn * 32 + nf * 8 + 2 * q;
            int h = col >> 6, d = col & 63;
            int s0 = sig16(d), s1 = sig16(d + 1);
#pragma unroll
            for (int rr = 0; rr < 2; rr++) {
                int m = brow + wm * 64 + mf * 16 + r + rr * 8;
                int b = m >> 10, nq = m & 1023;
                float v0 = tf32f(acc[mf][nf][rr * 2 + 0]);
                float v1 = tf32f(acc[mf][nf][rr * 2 + 1]);
                if (part < 2) {
                    float* dst = (part == 0) ? g_Q : g_K;
                    size_t base = (((size_t)(b * NHEADS + h)) * SEQ + nq) * HDIM;
                    dst[base + s0] = v0;
                    dst[base + s1] = v1;
                } else {
                    size_t pb = ((size_t)(b * NHEADS + h)) * HDIM;
                    g_Vt[(pb + d)     * SEQ + nq] = v0;
                    g_Vt[(pb + d + 1) * SEQ + nq] = v1;
                }
            }
        }
}

// ============================================================================
// Kernel 2: FUSED flash attention.
//  - grid (pair, q-tile) for mask L2 reuse; 2-stage cp.async KV ring
//  - K smem stride 80 -> conflict-free LDS.128 K-fragments (sigma16 d-dim)
//  - V smem stride 72, float2 loads (key-dim unpermuted; register-P key order)
//  - group-streamed no-max softmax, P in registers
// ============================================================================
#define KT 64
#define LDTK 80
#define LDTV 72
#define NITER (SEQ / KT)
#define STAGE_F (64 * LDTK + 64 * LDTV)    // 9728 floats

__global__ __launch_bounds__(256, 2) void flash_tc() {
    extern __shared__ float sm[];

    const int tid = threadIdx.x, lane = tid & 31, wid = tid >> 5;
    const int r = lane >> 2, q = lane & 3;
    const int pair = blockIdx.x;
    const int h = pair % NHEADS, b = pair / NHEADS;
    const int q0 = blockIdx.y * 128;

    const float* Qg = g_Q  + (size_t)pair * SEQ * HDIM;
    const float* Kg = g_K  + (size_t)pair * SEQ * HDIM;
    const float* Vg = g_Vt + (size_t)pair * HDIM * SEQ;
    const float* Mg = g_Msig + (size_t)h * SEQ * SEQ;

    const int crow = tid >> 4, cc = (tid & 15) * 4;

    auto copyKV = [&](int kb, int buf) {
        float* Kd = sm + buf * STAGE_F;
        float* Vd = Kd + 64 * LDTK;
        const float* Ksrc = Kg + (size_t)(kb * KT) * HDIM;
        const float* Vsrc = Vg + kb * KT;
#pragma unroll
        for (int p = 0; p < 4; p++) {
            int row = crow + p * 16;
            CP_ASYNC16(smem_u32(&Kd[row * LDTK + cc]), Ksrc + (size_t)row * HDIM + cc);
            CP_ASYNC16(smem_u32(&Vd[row * LDTV + cc]), Vsrc + (size_t)row * SEQ + cc);
        }
    };

    copyKV(0, 0); CP_COMMIT();
    copyKV(1, 1); CP_COMMIT();

    // ---- Q fragments via LDG.128 from sigma16-permuted global ----
    uint32_t qa[8][4];
    {
        const float* qr0 = Qg + (size_t)(q0 + wid * 16 + r) * HDIM + 4 * q;
        const float* qr1 = qr0 + 8 * HDIM;
#pragma unroll
        for (int blk = 0; blk < 4; blk++) {
            float4 v0 = *reinterpret_cast<const float4*>(qr0 + blk * 16);
            float4 v1 = *reinterpret_cast<const float4*>(qr1 + blk * 16);
            qa[2 * blk][0]     = __float_as_uint(v0.x);
            qa[2 * blk][1]     = __float_as_uint(v1.x);
            qa[2 * blk][2]     = __float_as_uint(v0.y);
            qa[2 * blk][3]     = __float_as_uint(v1.y);
            qa[2 * blk + 1][0] = __float_as_uint(v0.z);
            qa[2 * blk + 1][1] = __float_as_uint(v1.z);
            qa[2 * blk + 1][2] = __float_as_uint(v0.w);
            qa[2 * blk + 1][3] = __float_as_uint(v1.w);
        }
    }

    float od[8][4];
#pragma unroll
    for (int nf = 0; nf < 8; nf++)
#pragma unroll
        for (int i = 0; i < 4; i++) od[nf][i] = 0.f;
    float l0 = 0.f, l1 = 0.f;

    const int row_s0 = q0 + wid * 16 + r;
    const float* Mrow0 = Mg + (size_t)row_s0 * SEQ + 2 * q;
    const float* Mrow1 = Mrow0 + 8 * SEQ;

#pragma unroll 1
    for (int kb = 0; kb < NITER; kb++) {
        if (kb == NITER - 1) { CP_WAIT(0); } else { CP_WAIT(1); }
        __syncthreads();                 // stage kb visible everywhere

        const float* Ks = sm + (kb & 1) * STAGE_F;
        const float* Vs = Ks + 64 * LDTK;

        // ---- stream key-groups: S (LDS.128 K-frags, 2 chains) -> exp -> PV --
#pragma unroll
        for (int g = 0; g < 8; g++) {
            float sa[4] = {0.f, 0.f, 0.f, 0.f};
            float sb[4] = {0.f, 0.f, 0.f, 0.f};
            const float* Kr = &Ks[(g * 8 + r) * LDTK + 4 * q];
#pragma unroll
            for (int blk = 0; blk < 4; blk++) {
                float4 kv = *reinterpret_cast<const float4*>(Kr + blk * 16);
                uint32_t bf0[2] = { __float_as_uint(kv.x), __float_as_uint(kv.y) };
                uint32_t bf1[2] = { __float_as_uint(kv.z), __float_as_uint(kv.w) };
                mma_tf32(sa, qa[2 * blk],     bf0);
                mma_tf32(sb, qa[2 * blk + 1], bf1);
            }
            sa[0] += sb[0]; sa[1] += sb[1]; sa[2] += sb[2]; sa[3] += sb[3];

            int col = kb * KT + g * 8;
            float2 g0 = *reinterpret_cast<const float2*>(Mrow0 + col);
            float2 g1 = *reinterpret_cast<const float2*>(Mrow1 + col);
            float p00 = __expf(sa[0] * g0.x);
            float p01 = __expf(sa[1] * g0.y);
            float p10 = __expf(sa[2] * g1.x);
            float p11 = __expf(sa[3] * g1.y);
            l0 += p00 + p01; l1 += p10 + p11;

            uint32_t af[4] = { cvt_tf32(p00), cvt_tf32(p10),
                               cvt_tf32(p01), cvt_tf32(p11) };
            const float* Vr = &Vs[r * LDTV + g * 8 + 2 * q];
#pragma unroll
            for (int nf = 0; nf < 8; nf++) {
                float2 bv = *reinterpret_cast<const float2*>(Vr + nf * 8 * LDTV);
                uint32_t bf[2] = { __float_as_uint(bv.x), __float_as_uint(bv.y) };
                mma_tf32(od[nf], af, bf);
            }
        }

        if (kb + 2 < NITER) {
            __syncthreads();             // all warps done with this buffer
            copyKV(kb + 2, kb & 1);
            CP_COMMIT();
        }
    }

    // ---- normalize and write O (tf32, sigma16-permuted DIMC) ----
    l0 += __shfl_xor_sync(0xffffffffu, l0, 1);
    l0 += __shfl_xor_sync(0xffffffffu, l0, 2);
    l1 += __shfl_xor_sync(0xffffffffu, l1, 1);
    l1 += __shfl_xor_sync(0xffffffffu, l1, 2);
    float inv0 = 1.f / l0, inv1 = 1.f / l1;

    size_t orow0 = (size_t)b * SEQ + q0 + wid * 16 + r;
#pragma unroll
    for (int nf = 0; nf < 8; nf++) {
        int d0 = nf * 8 + 2 * q;
        int s0 = h * HDIM + sig16(d0);
        int s1 = h * HDIM + sig16(d0 + 1);
        g_O[orow0 * DIMC + s0]       = tf32f(od[nf][0] * inv0);
        g_O[orow0 * DIMC + s1]       = tf32f(od[nf][1] * inv0);
        g_O[(orow0 + 8) * DIMC + s0] = tf32f(od[nf][2] * inv1);
        g_O[(orow0 + 8) * DIMC + s1] = tf32f(od[nf][3] * inv1);
    }
}

// ============================================================================
// Kernel 3: out = O @ Wproj^T + bias (operands sigma16-permuted; output plain)
// ============================================================================
__global__ __launch_bounds__(256) void proj_tc(const float* __restrict__ bias,
                                               float* __restrict__ out) {
    extern __shared__ float smf[];
    float acc[4][4][4];
    int brow = blockIdx.y * 128, bcol = blockIdx.x * 128;
    gemm_core<128, 24, 4, 4, 2>(g_O + (size_t)brow * DIMC, DIMC,
                                g_Wp + (size_t)bcol * DIMC, DIMC, acc, smf);
    int lane = threadIdx.x & 31, wid = threadIdx.x >> 5;
    int wm = wid % 2, wn = wid / 2, r = lane >> 2, q = lane & 3;

#pragma unroll
    for (int mf = 0; mf < 4; mf++)
#pragma unroll
        for (int nf = 0; nf < 4; nf++) {
            int col = bcol + wn * 32 + nf * 8 + q * 2;
            float2 bb = *reinterpret_cast<const float2*>(&bias[col]);
#pragma unroll
            for (int rr = 0; rr < 2; rr++) {
                int row = brow + wm * 64 + mf * 16 + r + rr * 8;
                float v0 = acc[mf][nf][rr * 2 + 0] + bb.x;
                float v1 = acc[mf][nf][rr * 2 + 1] + bb.y;
                *reinterpret_cast<float2*>(&out[(size_t)row * DIMC + col]) = make_float2(v0, v1);
            }
        }
}

// ============================================================================
extern "C" void kernel_launch(void* const* d_in, const int* in_sizes, int n_in,
                              void* d_out, int out_size) {
    (void)in_sizes; (void)n_in; (void)out_size;
    const float* x        = (const float*)d_in[0];
    const float* w_qkv    = (const float*)d_in[1];
    const float* w_proj   = (const float*)d_in[2];
    const float* b_proj   = (const float*)d_in[3];
    const float* att_mask = (const float*)d_in[4];
    float* out = (float*)d_out;

    const int GEMM_SMEM  = (4 * 128 * LDK) * (int)sizeof(float);    // 98304
    const int FLASH_SMEM = (2 * STAGE_F) * (int)sizeof(float);      // 77824

    cudaFuncSetAttribute(qkv_tc,   cudaFuncAttributeMaxDynamicSharedMemorySize, GEMM_SMEM);
    cudaFuncSetAttribute(proj_tc,  cudaFuncAttributeMaxDynamicSharedMemorySize, GEMM_SMEM);
    cudaFuncSetAttribute(flash_tc, cudaFuncAttributeMaxDynamicSharedMemorySize, FLASH_SMEM);

    round_all<<<NB_X + NB_WQ + NB_WP, 256>>>(x, w_qkv, w_proj);
    presig   <<<(NHEADS * SEQ * SEQ) / 1024, 256>>>(att_mask);

    qkv_tc  <<<dim3(2304 / 128, MROWS / 128), 256, GEMM_SMEM>>>();
    flash_tc<<<dim3(PAIRS, SEQ / 128), 256, FLASH_SMEM>>>();
    proj_tc <<<dim3(DIMC / 128, MROWS / 128), 256, GEMM_SMEM>>>(b_proj, out);
}